// round 4
// baseline (speedup 1.0000x reference)
#include <cuda_runtime.h>
#include <cuda_bf16.h>
#include <math.h>
#include <cstdint>

// Problem constants
#define Bsz 4
#define Tsz 4096
#define Dsz 1024
#define Hsz 4
#define DKsz 256
#define DVsz 256
#define ROWS (Bsz*Tsz)        // 16384
#define WIN 16
#define NWIN (Tsz/WIN)        // 256
// per-(bh,window) precompute block: negW[256] | P[256] | coef[64]
#define WPSZ 576

// -------- static device scratch (no allocations allowed) --------
__device__ float g_q[ROWS * Dsz];
__device__ float g_k[ROWS * Dsz];
__device__ float g_v[ROWS * Dsz];
__device__ float g_g[ROWS * Dsz];
__device__ float g_o[ROWS * Dsz];
__device__ float g_beta[ROWS * Hsz];
__device__ float g_dec[ROWS * Hsz];
__device__ float g_wp[16 * NWIN * WPSZ];   // 9.4MB precompute
// bf16 split operands
__device__ __nv_bfloat16 g_xh[ROWS * Dsz];
__device__ __nv_bfloat16 g_xl[ROWS * Dsz];
__device__ __nv_bfloat16 g_yh[ROWS * Dsz];
__device__ __nv_bfloat16 g_yl[ROWS * Dsz];
__device__ __nv_bfloat16 g_wth[5 * Dsz * Dsz];
__device__ __nv_bfloat16 g_wtl[5 * Dsz * Dsz];

// ============================================================
// helpers (baseline PTX only)
// ============================================================
__device__ __forceinline__ uint32_t smem_to_u32(const void* p) {
    uint32_t a;
    asm("{ .reg .u64 t; cvta.to.shared.u64 t, %1; cvt.u32.u64 %0, t; }"
        : "=r"(a) : "l"(p));
    return a;
}
__device__ __forceinline__ void cp_async16(uint32_t s, const void* g) {
    asm volatile("cp.async.cg.shared.global [%0], [%1], 16;" :: "r"(s), "l"(g));
}
__device__ __forceinline__ void ldsm4(uint32_t& r0, uint32_t& r1, uint32_t& r2,
                                      uint32_t& r3, uint32_t addr) {
    asm volatile("ldmatrix.sync.aligned.m8n8.x4.shared.b16 {%0,%1,%2,%3}, [%4];"
                 : "=r"(r0), "=r"(r1), "=r"(r2), "=r"(r3) : "r"(addr));
}
__device__ __forceinline__ void mma16816(float* c, const uint32_t* a,
                                         uint32_t b0, uint32_t b1) {
    asm volatile(
        "mma.sync.aligned.m16n8k16.row.col.f32.bf16.bf16.f32 "
        "{%0,%1,%2,%3}, {%4,%5,%6,%7}, {%8,%9}, {%0,%1,%2,%3};"
        : "+f"(c[0]), "+f"(c[1]), "+f"(c[2]), "+f"(c[3])
        : "r"(a[0]), "r"(a[1]), "r"(a[2]), "r"(a[3]), "r"(b0), "r"(b1));
}

// ============================================================
// fp32 -> (hi, lo) bf16 split
// ============================================================
__global__ __launch_bounds__(256) void split_kernel(
    const float* __restrict__ src, __nv_bfloat16* __restrict__ hi,
    __nv_bfloat16* __restrict__ lo)
{
    const int i = blockIdx.x * 256 + threadIdx.x;
    float4 v = ((const float4*)src)[i];
    __nv_bfloat16 h0 = __float2bfloat16(v.x), h1 = __float2bfloat16(v.y);
    __nv_bfloat16 h2 = __float2bfloat16(v.z), h3 = __float2bfloat16(v.w);
    __nv_bfloat16 l0 = __float2bfloat16(v.x - __bfloat162float(h0));
    __nv_bfloat16 l1 = __float2bfloat16(v.y - __bfloat162float(h1));
    __nv_bfloat16 l2 = __float2bfloat16(v.z - __bfloat162float(h2));
    __nv_bfloat16 l3 = __float2bfloat16(v.w - __bfloat162float(h3));
    ((__nv_bfloat162*)hi)[i*2]   = __halves2bfloat162(h0, h1);
    ((__nv_bfloat162*)hi)[i*2+1] = __halves2bfloat162(h2, h3);
    ((__nv_bfloat162*)lo)[i*2]   = __halves2bfloat162(l0, l1);
    ((__nv_bfloat162*)lo)[i*2+1] = __halves2bfloat162(l2, l3);
}

// ============================================================
// transpose 1024x1024 fp32 weight, split into hi/lo bf16
// ============================================================
__global__ __launch_bounds__(256) void transpose_split_kernel(
    const float* __restrict__ W, __nv_bfloat16* __restrict__ Th,
    __nv_bfloat16* __restrict__ Tl)
{
    __shared__ float tile[32][33];
    const int n0 = blockIdx.x * 32, k0 = blockIdx.y * 32;
    const int tx = threadIdx.x & 31, ty = threadIdx.x >> 5;
#pragma unroll
    for (int r = ty; r < 32; r += 8)
        tile[r][tx] = W[(size_t)(k0 + r) * Dsz + n0 + tx];
    __syncthreads();
#pragma unroll
    for (int r = ty; r < 32; r += 8) {
        float v = tile[tx][r];
        __nv_bfloat16 h = __float2bfloat16(v);
        __nv_bfloat16 l = __float2bfloat16(v - __bfloat162float(h));
        size_t o = (size_t)(n0 + r) * Dsz + k0 + tx;
        Th[o] = h;
        Tl[o] = l;
    }
}

// ============================================================
// bf16x3 GEMM via mma.sync (unchanged from R3)
// ============================================================
#define TILE_BYTES (128*80)
#define STAGE_BYTES (4*TILE_BYTES)
#define GEMM_SMEM (2*STAGE_BYTES)

__global__ __launch_bounds__(256, 1) void gemm_mma_bf16x3(
    const __nv_bfloat16* __restrict__ Ah, const __nv_bfloat16* __restrict__ Al,
    const __nv_bfloat16* __restrict__ Bh, const __nv_bfloat16* __restrict__ Bl,
    float* __restrict__ C)
{
    extern __shared__ char sm[];
    const int tid = threadIdx.x;
    const int wid = tid >> 5, lane = tid & 31;
    const int bx = blockIdx.x, by = blockIdx.y;
    const int wm = wid & 3;
    const int wn = wid >> 2;

    const uint32_t sbase = smem_to_u32(sm);

    const __nv_bfloat16* srcs[4] = {
        Ah + (size_t)(by * 128) * Dsz,
        Al + (size_t)(by * 128) * Dsz,
        Bh + (size_t)(bx * 128) * Dsz,
        Bl + (size_t)(bx * 128) * Dsz
    };

    float acc[2][8][4];
#pragma unroll
    for (int mt = 0; mt < 2; mt++)
#pragma unroll
        for (int nt = 0; nt < 8; nt++)
#pragma unroll
            for (int i = 0; i < 4; i++) acc[mt][nt][i] = 0.f;

    auto load_stage = [&](int kc) {
        const uint32_t sdst = sbase + (kc & 1) * STAGE_BYTES;
        const int k0 = kc * 32;
#pragma unroll
        for (int t = 0; t < 4; t++) {
            const __nv_bfloat16* src = srcs[t];
#pragma unroll
            for (int i = 0; i < 2; i++) {
                int id = i * 256 + tid;
                int r = id >> 2, c = id & 3;
                cp_async16(sdst + t * TILE_BYTES + r * 80 + c * 16,
                           src + (size_t)r * Dsz + k0 + c * 8);
            }
        }
        asm volatile("cp.async.commit_group;" ::: "memory");
    };

    load_stage(0);

    const int lrow = lane & 15;
    const int lcolb = (lane >> 4) * 16;

    for (int kc = 0; kc < 32; kc++) {
        if (kc < 31) load_stage(kc + 1);
        else asm volatile("cp.async.commit_group;" ::: "memory");
        asm volatile("cp.async.wait_group 1;" ::: "memory");
        __syncthreads();

        const uint32_t s = sbase + (kc & 1) * STAGE_BYTES;
        const uint32_t sAh = s;
        const uint32_t sAl = s + TILE_BYTES;
        const uint32_t sBh = s + 2 * TILE_BYTES;
        const uint32_t sBl = s + 3 * TILE_BYTES;

#pragma unroll
        for (int ks = 0; ks < 2; ks++) {
            const uint32_t cb = ks * 32 + lcolb;
            uint32_t ah[2][4], bh[4][4], al[2][4], bl[4][4];
#pragma unroll
            for (int mt = 0; mt < 2; mt++)
                ldsm4(ah[mt][0], ah[mt][1], ah[mt][2], ah[mt][3],
                      sAh + (wm * 32 + mt * 16 + lrow) * 80 + cb);
#pragma unroll
            for (int bt = 0; bt < 4; bt++)
                ldsm4(bh[bt][0], bh[bt][1], bh[bt][2], bh[bt][3],
                      sBh + (wn * 64 + bt * 16 + lrow) * 80 + cb);
#pragma unroll
            for (int mt = 0; mt < 2; mt++)
#pragma unroll
                for (int bt = 0; bt < 4; bt++) {
                    mma16816(acc[mt][bt*2],   ah[mt], bh[bt][0], bh[bt][2]);
                    mma16816(acc[mt][bt*2+1], ah[mt], bh[bt][1], bh[bt][3]);
                }
#pragma unroll
            for (int mt = 0; mt < 2; mt++)
                ldsm4(al[mt][0], al[mt][1], al[mt][2], al[mt][3],
                      sAl + (wm * 32 + mt * 16 + lrow) * 80 + cb);
#pragma unroll
            for (int mt = 0; mt < 2; mt++)
#pragma unroll
                for (int bt = 0; bt < 4; bt++) {
                    mma16816(acc[mt][bt*2],   al[mt], bh[bt][0], bh[bt][2]);
                    mma16816(acc[mt][bt*2+1], al[mt], bh[bt][1], bh[bt][3]);
                }
#pragma unroll
            for (int bt = 0; bt < 4; bt++)
                ldsm4(bl[bt][0], bl[bt][1], bl[bt][2], bl[bt][3],
                      sBl + (wn * 64 + bt * 16 + lrow) * 80 + cb);
#pragma unroll
            for (int mt = 0; mt < 2; mt++)
#pragma unroll
                for (int bt = 0; bt < 4; bt++) {
                    mma16816(acc[mt][bt*2],   ah[mt], bl[bt][0], bl[bt][2]);
                    mma16816(acc[mt][bt*2+1], ah[mt], bl[bt][1], bl[bt][3]);
                }
        }
        __syncthreads();
    }

    const int crow = by * 128 + wm * 32 + (lane >> 2);
    const int ccol = bx * 128 + wn * 64 + (lane & 3) * 2;
#pragma unroll
    for (int mt = 0; mt < 2; mt++) {
#pragma unroll
        for (int nt = 0; nt < 8; nt++) {
            float* p0 = C + (size_t)(crow + mt * 16) * Dsz + ccol + nt * 8;
            float* p1 = p0 + 8 * Dsz;
            *(float2*)p0 = make_float2(acc[mt][nt][0], acc[mt][nt][1]);
            *(float2*)p1 = make_float2(acc[mt][nt][2], acc[mt][nt][3]);
        }
    }
}

// ============================================================
// beta / dec projections (unchanged)
// ============================================================
__global__ __launch_bounds__(256) void beta_dec_kernel(
    const float* __restrict__ x, const float* __restrict__ Wb,
    const float* __restrict__ Wa, const float* __restrict__ A_log,
    const float* __restrict__ dt_bias,
    float* __restrict__ beta, float* __restrict__ dec)
{
    const int row = blockIdx.x * 8 + (threadIdx.x >> 5);
    const int lane = threadIdx.x & 31;
    if (row >= ROWS) return;

    float accb[4] = {0,0,0,0}, acca[4] = {0,0,0,0};
    const float* xr = x + (size_t)row * Dsz;
    const float4* Wb4 = (const float4*)Wb;
    const float4* Wa4 = (const float4*)Wa;

    for (int i = lane; i < Dsz; i += 32) {
        float xv = xr[i];
        float4 wb = Wb4[i];
        float4 wa = Wa4[i];
        accb[0] += xv * wb.x; accb[1] += xv * wb.y;
        accb[2] += xv * wb.z; accb[3] += xv * wb.w;
        acca[0] += xv * wa.x; acca[1] += xv * wa.y;
        acca[2] += xv * wa.z; acca[3] += xv * wa.w;
    }
#pragma unroll
    for (int off = 16; off; off >>= 1) {
#pragma unroll
        for (int h = 0; h < 4; h++) {
            accb[h] += __shfl_xor_sync(0xffffffffu, accb[h], off);
            acca[h] += __shfl_xor_sync(0xffffffffu, acca[h], off);
        }
    }
    if (lane < 4) {
        int h = lane;
        float bv = 1.f / (1.f + expf(-accb[h]));
        float a = acca[h] + dt_bias[h];
        float sp = fmaxf(a, 0.f) + log1pf(expf(-fabsf(a)));
        float dv = expf(-expf(A_log[h]) * sp);
        beta[(size_t)row * Hsz + h] = bv;
        dec [(size_t)row * Hsz + h] = dv;
    }
}

// ============================================================
// L2-normalize q and k (unchanged)
// ============================================================
__global__ __launch_bounds__(256) void norm_qk_kernel(float* __restrict__ q,
                                                      float* __restrict__ k)
{
    const int row = blockIdx.x * 8 + (threadIdx.x >> 5);
    const int lane = threadIdx.x & 31;
    float4* qr = (float4*)(q + (size_t)row * DKsz);
    float4* kr = (float4*)(k + (size_t)row * DKsz);
    float4 q0 = qr[lane * 2], q1 = qr[lane * 2 + 1];
    float4 k0 = kr[lane * 2], k1 = kr[lane * 2 + 1];

    float sq = q0.x*q0.x + q0.y*q0.y + q0.z*q0.z + q0.w*q0.w
             + q1.x*q1.x + q1.y*q1.y + q1.z*q1.z + q1.w*q1.w;
    float sk = k0.x*k0.x + k0.y*k0.y + k0.z*k0.z + k0.w*k0.w
             + k1.x*k1.x + k1.y*k1.y + k1.z*k1.z + k1.w*k1.w;
#pragma unroll
    for (int off = 16; off; off >>= 1) {
        sq += __shfl_xor_sync(0xffffffffu, sq, off);
        sk += __shfl_xor_sync(0xffffffffu, sk, off);
    }
    float qs = rsqrtf(sq + 1e-6f) * 0.0625f;
    float ks = rsqrtf(sk + 1e-6f);
    q0.x*=qs; q0.y*=qs; q0.z*=qs; q0.w*=qs;
    q1.x*=qs; q1.y*=qs; q1.z*=qs; q1.w*=qs;
    k0.x*=ks; k0.y*=ks; k0.z*=ks; k0.w*=ks;
    k1.x*=ks; k1.y*=ks; k1.z*=ks; k1.w*=ks;
    qr[lane * 2] = q0; qr[lane * 2 + 1] = q1;
    kr[lane * 2] = k0; kr[lane * 2 + 1] = k1;
}

// ============================================================
// Kernel A: per-(bh,window) UT-transform precompute.
// negW[i][j] = -beta_i * ratio(i,j) * (k_i . k_j)    (j < i)
// P[i][j]    =          ratio(i,j) * (q_i . k_j)     (j <= i)
// ratio(i,j) = prod_{m=j+1..i} dec_m  (stable descending products)
// coef = { beta[16], beta*gamma[16], gamma[16], c[16]=gamma15/gamma_j }
// ============================================================
__global__ __launch_bounds__(256) void ut_precompute_kernel(
    const float* __restrict__ k, const float* __restrict__ q,
    const float* __restrict__ beta, const float* __restrict__ dec,
    float* __restrict__ wp)
{
    __shared__ float sk[WIN][DKsz];
    __shared__ float sq[WIN][DKsz];
    __shared__ float sdec[WIN], sbeta[WIN];

    const int w = blockIdx.x;          // window
    const int bh = blockIdx.y;         // 0..15
    const int b = bh >> 2, h = bh & 3;
    const int t0 = w * WIN;
    const int tid = threadIdx.x;
    const int wid = tid >> 5, lane = tid & 31;

    const size_t rowbase = (size_t)b * Tsz * Dsz + h * DKsz;

    // cooperative tile load
#pragma unroll
    for (int r = 0; r < 4; r++) {
        int idx = r * 256 + tid;
        int ss = idx >> 6;
        int d4 = (idx & 63) * 4;
        size_t gaddr = rowbase + (size_t)(t0 + ss) * Dsz + d4;
        *(float4*)&sk[ss][d4] = *(const float4*)(k + gaddr);
        *(float4*)&sq[ss][d4] = *(const float4*)(q + gaddr);
    }
    if (tid < WIN) {
        size_t bidx = (size_t)(b * Tsz + t0 + tid) * Hsz + h;
        sdec[tid] = dec[bidx];
        sbeta[tid] = beta[bidx];
    }
    __syncthreads();

    float* dst = wp + (size_t)(bh * NWIN + w) * WPSZ;

    // thread 0: coef block (serial, tiny)
    if (tid == 0) {
        float gam[WIN];
        float g = 1.f;
#pragma unroll
        for (int i = 0; i < WIN; i++) { g *= sdec[i]; gam[i] = g; }
        float c = 1.f;
        float cc[WIN];
        cc[WIN-1] = 1.f;
        for (int j = WIN - 2; j >= 0; j--) { c *= sdec[j+1]; cc[j] = c; }
#pragma unroll
        for (int i = 0; i < WIN; i++) {
            dst[512 + i]      = sbeta[i];
            dst[512 + 16 + i] = sbeta[i] * gam[i];
            dst[512 + 32 + i] = gam[i];
            dst[512 + 48 + i] = cc[i];
        }
    }

    // 8 warps, each handles i-rows {2*wid, 2*wid+1}
#pragma unroll
    for (int ii = 0; ii < 2; ii++) {
        const int i = wid * 2 + ii;
        float4 ka = *(const float4*)&sk[i][lane * 8];
        float4 kb = *(const float4*)&sk[i][lane * 8 + 4];
        float4 qa = *(const float4*)&sq[i][lane * 8];
        float4 qb = *(const float4*)&sq[i][lane * 8 + 4];

        float ratio = 1.f;
        const float bi = sbeta[i];
        for (int j = i; j >= 0; j--) {
            if (j < i) ratio *= sdec[j + 1];
            const float4 xa = *(const float4*)&sk[j][lane * 8];
            const float4 xb = *(const float4*)&sk[j][lane * 8 + 4];
            float dk = ka.x*xa.x + ka.y*xa.y + ka.z*xa.z + ka.w*xa.w
                     + kb.x*xb.x + kb.y*xb.y + kb.z*xb.z + kb.w*xb.w;
            float dq = qa.x*xa.x + qa.y*xa.y + qa.z*xa.z + qa.w*xa.w
                     + qb.x*xb.x + qb.y*xb.y + qb.z*xb.z + qb.w*xb.w;
#pragma unroll
            for (int off = 16; off; off >>= 1) {
                dk += __shfl_xor_sync(0xffffffffu, dk, off);
                dq += __shfl_xor_sync(0xffffffffu, dq, off);
            }
            if (lane == 0) {
                dst[256 + i * 16 + j] = ratio * dq;       // P (incl diag)
                if (j < i) dst[i * 16 + j] = -bi * ratio * dk;  // negW
            }
        }
    }
}

// ============================================================
// Kernel B: windowed column-parallel scan.
// Warp = one state column j. Lane owns rows lane*8 .. lane*8+7.
// Per window: batched (m,z) dots via 31-shfl multi-butterfly,
// scalar u-chain (lanes 0-15) + o accumulation (lanes 16-31),
// then rank-16 state update.
// ============================================================
__global__ __launch_bounds__(256) void recurrence2_kernel(
    const float* __restrict__ q, const float* __restrict__ k,
    const float* __restrict__ v, const float* __restrict__ wp,
    float* __restrict__ o)
{
    __shared__ float sk[WIN][DKsz];    // 16KB
    __shared__ float sq[WIN][DKsz];    // 16KB
    __shared__ float sv[WIN][8];
    __shared__ float sWP[WPSZ];        // negW | P | coef
    __shared__ float so[WIN][8];

    const int cta = blockIdx.x;        // 512
    const int bh = cta >> 5;
    const int jg = cta & 31;
    const int b = bh >> 2, h = bh & 3;
    const int tid = threadIdx.x;
    const int w = tid >> 5, lane = tid & 31;
    const int li = lane & 15;

    float s[8];
#pragma unroll
    for (int i = 0; i < 8; i++) s[i] = 0.f;

    const size_t rowbase = (size_t)b * Tsz * Dsz + h * DKsz;
    const float* wpb = wp + (size_t)bh * NWIN * WPSZ;

    for (int wi = 0; wi < NWIN; wi++) {
        const int t0 = wi * WIN;
        __syncthreads();
        // ---- cooperative loads ----
#pragma unroll
        for (int r = 0; r < 4; r++) {
            int idx = r * 256 + tid;
            int ss = idx >> 6;
            int d4 = (idx & 63) * 4;
            size_t gaddr = rowbase + (size_t)(t0 + ss) * Dsz + d4;
            *(float4*)&sk[ss][d4] = *(const float4*)(k + gaddr);
            *(float4*)&sq[ss][d4] = *(const float4*)(q + gaddr);
        }
        if (tid < 128) {
            int ss = tid >> 3, jj = tid & 7;
            sv[ss][jj] = v[rowbase + (size_t)(t0 + ss) * Dsz + jg * 8 + jj];
        }
        if (tid < 144)
            *(float4*)&sWP[tid * 4] =
                *(const float4*)(wpb + (size_t)wi * WPSZ + tid * 4);
        __syncthreads();

        // ---- phase 1: batched partial dots m_i (v=i), z_i (v=16+i) ----
        float p[32];
#pragma unroll
        for (int i = 0; i < WIN; i++) {
            const float4 ka = *(const float4*)&sk[i][lane * 8];
            const float4 kb = *(const float4*)&sk[i][lane * 8 + 4];
            const float4 qa = *(const float4*)&sq[i][lane * 8];
            const float4 qb = *(const float4*)&sq[i][lane * 8 + 4];
            p[i] = ka.x*s[0] + ka.y*s[1] + ka.z*s[2] + ka.w*s[3]
                 + kb.x*s[4] + kb.y*s[5] + kb.z*s[6] + kb.w*s[7];
            p[16+i] = qa.x*s[0] + qa.y*s[1] + qa.z*s[2] + qa.w*s[3]
                    + qb.x*s[4] + qb.y*s[5] + qb.z*s[6] + qb.w*s[7];
        }
        // multi-value butterfly: 31 shfl reduces all 32 values;
        // lane l ends with value index l in p[0].
#pragma unroll
        for (int bb = 16; bb; bb >>= 1) {
#pragma unroll
            for (int vv = 0; vv < 32; vv++) {
                if (vv < bb) {
                    float a0 = p[vv], a1 = p[vv + bb];
                    float sent = (lane & bb) ? a0 : a1;
                    float recv = __shfl_xor_sync(0xffffffffu, sent, bb);
                    p[vv] = ((lane & bb) ? a1 : a0) + recv;
                }
            }
        }
        // lane<16: p[0]=m_li ; lane>=16: p[0]=z_li

        // ---- preload per-lane W/P row + coefs ----
        const float* rowb = sWP + ((lane < 16) ? 0 : 256) + li * 16;
        float wrow[16];
#pragma unroll
        for (int r4 = 0; r4 < 4; r4++)
            *(float4*)&wrow[r4 * 4] = *(const float4*)(rowb + r4 * 4);

        float acc;
        if (lane < 16) {
            const float cb  = sWP[512 + li];        // beta_i
            const float cbg = sWP[512 + 16 + li];   // beta_i*gamma_i
            acc = cb * sv[li][w] - cbg * p[0];      // b_i
        } else {
            const float cg = sWP[512 + 32 + li];    // gamma_i
            acc = cg * p[0];                        // gamma_i * z_i
        }

        // ---- phase 2+3: scalar u-chain + o accumulation ----
        float u_all[16];
#pragma unroll
        for (int j = 0; j < WIN; j++) {
            float uj = __shfl_sync(0xffffffffu, acc, j);
            u_all[j] = uj;
            int thresh = j + ((lane < 16) ? 1 : 0);
            if (li >= thresh) acc = fmaf(wrow[j], uj, acc);
        }
        if (lane >= 16) so[li][w] = acc;   // o_i for this column

        // ---- phase 4: state update s = g15*s + sum_j c_j*u_j*k_j ----
        const float g15 = sWP[512 + 32 + 15];
#pragma unroll
        for (int r = 0; r < 8; r++) s[r] *= g15;
#pragma unroll
        for (int j = 0; j < WIN; j++) {
            const float uc = sWP[512 + 48 + j] * u_all[j];
            const float4 ka = *(const float4*)&sk[j][lane * 8];
            const float4 kb = *(const float4*)&sk[j][lane * 8 + 4];
            s[0] = fmaf(ka.x, uc, s[0]); s[1] = fmaf(ka.y, uc, s[1]);
            s[2] = fmaf(ka.z, uc, s[2]); s[3] = fmaf(ka.w, uc, s[3]);
            s[4] = fmaf(kb.x, uc, s[4]); s[5] = fmaf(kb.y, uc, s[5]);
            s[6] = fmaf(kb.z, uc, s[6]); s[7] = fmaf(kb.w, uc, s[7]);
        }

        __syncthreads();
        // ---- coalesced o write ----
        if (tid < 128) {
            int t = tid >> 3, c = tid & 7;
            o[rowbase + (size_t)(t0 + t) * Dsz + jg * 8 + c] = so[t][c];
        }
    }
}

// ============================================================
// Gated RMSNorm (unchanged)
// ============================================================
__global__ __launch_bounds__(256) void gate_norm_kernel(
    const float* __restrict__ o, const float* __restrict__ g,
    const float* __restrict__ norm_w, float* __restrict__ out)
{
    const int row = blockIdx.x * 8 + (threadIdx.x >> 5);
    const int lane = threadIdx.x & 31;
    const float4* orow = (const float4*)(o + (size_t)row * DVsz);
    float4 o0 = orow[lane * 2], o1 = orow[lane * 2 + 1];

    float ss = o0.x*o0.x + o0.y*o0.y + o0.z*o0.z + o0.w*o0.w
             + o1.x*o1.x + o1.y*o1.y + o1.z*o1.z + o1.w*o1.w;
#pragma unroll
    for (int off = 16; off; off >>= 1)
        ss += __shfl_xor_sync(0xffffffffu, ss, off);
    float r = rsqrtf(ss * (1.f / 256.f) + 1e-5f);

    const float4* nw = (const float4*)norm_w;
    float4 w0 = nw[lane * 2], w1 = nw[lane * 2 + 1];
    const float4* grow = (const float4*)(g + (size_t)row * DVsz);
    float4 g0 = grow[lane * 2], g1 = grow[lane * 2 + 1];

    float4 r0, r1;
    r0.x = o0.x * r * w0.x * (g0.x / (1.f + expf(-g0.x)));
    r0.y = o0.y * r * w0.y * (g0.y / (1.f + expf(-g0.y)));
    r0.z = o0.z * r * w0.z * (g0.z / (1.f + expf(-g0.z)));
    r0.w = o0.w * r * w0.w * (g0.w / (1.f + expf(-g0.w)));
    r1.x = o1.x * r * w1.x * (g1.x / (1.f + expf(-g1.x)));
    r1.y = o1.y * r * w1.y * (g1.y / (1.f + expf(-g1.y)));
    r1.z = o1.z * r * w1.z * (g1.z / (1.f + expf(-g1.z)));
    r1.w = o1.w * r * w1.w * (g1.w / (1.f + expf(-g1.w)));

    float4* outr = (float4*)(out + (size_t)row * DVsz);
    outr[lane * 2] = r0;
    outr[lane * 2 + 1] = r1;
}

// ============================================================
// host launch
// ============================================================
extern "C" void kernel_launch(void* const* d_in, const int* in_sizes, int n_in,
                              void* d_out, int out_size)
{
    const float* x       = (const float*)d_in[0];
    const float* Wq      = (const float*)d_in[1];
    const float* Wk      = (const float*)d_in[2];
    const float* Wv      = (const float*)d_in[3];
    const float* Wb      = (const float*)d_in[4];
    const float* Wa      = (const float*)d_in[5];
    const float* A_log   = (const float*)d_in[6];
    const float* dt_bias = (const float*)d_in[7];
    const float* Wg      = (const float*)d_in[8];
    const float* norm_w  = (const float*)d_in[9];
    const float* Wo      = (const float*)d_in[10];
    float* out = (float*)d_out;

    float *q, *k, *v, *g, *o, *beta, *dec, *wpb;
    cudaGetSymbolAddress((void**)&q, g_q);
    cudaGetSymbolAddress((void**)&k, g_k);
    cudaGetSymbolAddress((void**)&v, g_v);
    cudaGetSymbolAddress((void**)&g, g_g);
    cudaGetSymbolAddress((void**)&o, g_o);
    cudaGetSymbolAddress((void**)&beta, g_beta);
    cudaGetSymbolAddress((void**)&dec, g_dec);
    cudaGetSymbolAddress((void**)&wpb, g_wp);
    __nv_bfloat16 *xh, *xl, *yh, *yl, *wth, *wtl;
    cudaGetSymbolAddress((void**)&xh, g_xh);
    cudaGetSymbolAddress((void**)&xl, g_xl);
    cudaGetSymbolAddress((void**)&yh, g_yh);
    cudaGetSymbolAddress((void**)&yl, g_yl);
    cudaGetSymbolAddress((void**)&wth, g_wth);
    cudaGetSymbolAddress((void**)&wtl, g_wtl);

    cudaFuncSetAttribute(gemm_mma_bf16x3,
                         cudaFuncAttributeMaxDynamicSharedMemorySize,
                         GEMM_SMEM);

    dim3 tgrid(Dsz / 32, Dsz / 32);
    transpose_split_kernel<<<tgrid, 256>>>(Wq, wth + 0*Dsz*Dsz, wtl + 0*Dsz*Dsz);
    transpose_split_kernel<<<tgrid, 256>>>(Wk, wth + 1*Dsz*Dsz, wtl + 1*Dsz*Dsz);
    transpose_split_kernel<<<tgrid, 256>>>(Wv, wth + 2*Dsz*Dsz, wtl + 2*Dsz*Dsz);
    transpose_split_kernel<<<tgrid, 256>>>(Wg, wth + 3*Dsz*Dsz, wtl + 3*Dsz*Dsz);
    transpose_split_kernel<<<tgrid, 256>>>(Wo, wth + 4*Dsz*Dsz, wtl + 4*Dsz*Dsz);
    split_kernel<<<(ROWS * Dsz / 4) / 256, 256>>>(x, xh, xl);

    dim3 ggrid(Dsz / 128, ROWS / 128);
    gemm_mma_bf16x3<<<ggrid, 256, GEMM_SMEM>>>(xh, xl, wth + 0*Dsz*Dsz, wtl + 0*Dsz*Dsz, q);
    gemm_mma_bf16x3<<<ggrid, 256, GEMM_SMEM>>>(xh, xl, wth + 1*Dsz*Dsz, wtl + 1*Dsz*Dsz, k);
    gemm_mma_bf16x3<<<ggrid, 256, GEMM_SMEM>>>(xh, xl, wth + 2*Dsz*Dsz, wtl + 2*Dsz*Dsz, v);
    gemm_mma_bf16x3<<<ggrid, 256, GEMM_SMEM>>>(xh, xl, wth + 3*Dsz*Dsz, wtl + 3*Dsz*Dsz, g);

    beta_dec_kernel<<<ROWS / 8, 256>>>(x, Wb, Wa, A_log, dt_bias, beta, dec);
    norm_qk_kernel<<<(ROWS * Hsz) / 8, 256>>>(q, k);

    // windowed UT transform precompute + scan
    ut_precompute_kernel<<<dim3(NWIN, 16), 256>>>(k, q, beta, dec, wpb);
    recurrence2_kernel<<<Bsz * Hsz * 32, 256>>>(q, k, v, wpb, o);

    gate_norm_kernel<<<(ROWS * Hsz) / 8, 256>>>(o, g, norm_w, q);
    split_kernel<<<(ROWS * Dsz / 4) / 256, 256>>>(q, yh, yl);
    gemm_mma_bf16x3<<<ggrid, 256, GEMM_SMEM>>>(yh, yl, wth + 4*Dsz*Dsz, wtl + 4*Dsz*Dsz, out);
}

// round 5
// speedup vs baseline: 1.6421x; 1.6421x over previous
#include <cuda_runtime.h>
#include <cuda_bf16.h>
#include <math.h>
#include <cstdint>

// Problem constants
#define Bsz 4
#define Tsz 4096
#define Dsz 1024
#define Hsz 4
#define DKsz 256
#define DVsz 256
#define ROWS (Bsz*Tsz)        // 16384
#define STEPS 16

// -------- static device scratch (no allocations allowed) --------
__device__ float g_q[ROWS * Dsz];
__device__ float g_k[ROWS * Dsz];
__device__ float g_v[ROWS * Dsz];
__device__ float g_g[ROWS * Dsz];
__device__ float g_o[ROWS * Dsz];
__device__ float g_beta[ROWS * Hsz];
__device__ float g_dec[ROWS * Hsz];
// bf16 split operands
__device__ __nv_bfloat16 g_xh[ROWS * Dsz];
__device__ __nv_bfloat16 g_xl[ROWS * Dsz];
__device__ __nv_bfloat16 g_yh[ROWS * Dsz];
__device__ __nv_bfloat16 g_yl[ROWS * Dsz];
__device__ __nv_bfloat16 g_wth[5 * Dsz * Dsz];
__device__ __nv_bfloat16 g_wtl[5 * Dsz * Dsz];

// ============================================================
// helpers (baseline PTX only)
// ============================================================
__device__ __forceinline__ uint32_t smem_to_u32(const void* p) {
    uint32_t a;
    asm("{ .reg .u64 t; cvta.to.shared.u64 t, %1; cvt.u32.u64 %0, t; }"
        : "=r"(a) : "l"(p));
    return a;
}
__device__ __forceinline__ void cp_async16(uint32_t s, const void* g) {
    asm volatile("cp.async.cg.shared.global [%0], [%1], 16;" :: "r"(s), "l"(g));
}
__device__ __forceinline__ void ldsm4(uint32_t& r0, uint32_t& r1, uint32_t& r2,
                                      uint32_t& r3, uint32_t addr) {
    asm volatile("ldmatrix.sync.aligned.m8n8.x4.shared.b16 {%0,%1,%2,%3}, [%4];"
                 : "=r"(r0), "=r"(r1), "=r"(r2), "=r"(r3) : "r"(addr));
}
__device__ __forceinline__ void mma16816(float* c, const uint32_t* a,
                                         uint32_t b0, uint32_t b1) {
    asm volatile(
        "mma.sync.aligned.m16n8k16.row.col.f32.bf16.bf16.f32 "
        "{%0,%1,%2,%3}, {%4,%5,%6,%7}, {%8,%9}, {%0,%1,%2,%3};"
        : "+f"(c[0]), "+f"(c[1]), "+f"(c[2]), "+f"(c[3])
        : "r"(a[0]), "r"(a[1]), "r"(a[2]), "r"(a[3]), "r"(b0), "r"(b1));
}
// ---- packed f32x2 (sm_100+ base ISA) ----
typedef unsigned long long u64t;
__device__ __forceinline__ u64t pack2(float x) {
    u64t r;
    asm("mov.b64 %0, {%1, %1};" : "=l"(r) : "f"(x));
    return r;
}
__device__ __forceinline__ void fma2(u64t& d, u64t a, u64t b, u64t c) {
    asm("fma.rn.f32x2 %0, %1, %2, %3;" : "=l"(d) : "l"(a), "l"(b), "l"(c));
}
__device__ __forceinline__ void mul2(u64t& d, u64t a, u64t b) {
    asm("mul.rn.f32x2 %0, %1, %2;" : "=l"(d) : "l"(a), "l"(b));
}
__device__ __forceinline__ void add2(u64t& d, u64t a, u64t b) {
    asm("add.rn.f32x2 %0, %1, %2;" : "=l"(d) : "l"(a), "l"(b));
}
__device__ __forceinline__ float sum2(u64t a) {
    float lo, hi;
    asm("mov.b64 {%0, %1}, %2;" : "=f"(lo), "=f"(hi) : "l"(a));
    return lo + hi;
}

// ============================================================
// fp32 -> (hi, lo) bf16 split
// ============================================================
__global__ __launch_bounds__(256) void split_kernel(
    const float* __restrict__ src, __nv_bfloat16* __restrict__ hi,
    __nv_bfloat16* __restrict__ lo)
{
    const int i = blockIdx.x * 256 + threadIdx.x;
    float4 v = ((const float4*)src)[i];
    __nv_bfloat16 h0 = __float2bfloat16(v.x), h1 = __float2bfloat16(v.y);
    __nv_bfloat16 h2 = __float2bfloat16(v.z), h3 = __float2bfloat16(v.w);
    __nv_bfloat16 l0 = __float2bfloat16(v.x - __bfloat162float(h0));
    __nv_bfloat16 l1 = __float2bfloat16(v.y - __bfloat162float(h1));
    __nv_bfloat16 l2 = __float2bfloat16(v.z - __bfloat162float(h2));
    __nv_bfloat16 l3 = __float2bfloat16(v.w - __bfloat162float(h3));
    ((__nv_bfloat162*)hi)[i*2]   = __halves2bfloat162(h0, h1);
    ((__nv_bfloat162*)hi)[i*2+1] = __halves2bfloat162(h2, h3);
    ((__nv_bfloat162*)lo)[i*2]   = __halves2bfloat162(l0, l1);
    ((__nv_bfloat162*)lo)[i*2+1] = __halves2bfloat162(l2, l3);
}

// ============================================================
// transpose 1024x1024 fp32 weight, split into hi/lo bf16
// ============================================================
__global__ __launch_bounds__(256) void transpose_split_kernel(
    const float* __restrict__ W, __nv_bfloat16* __restrict__ Th,
    __nv_bfloat16* __restrict__ Tl)
{
    __shared__ float tile[32][33];
    const int n0 = blockIdx.x * 32, k0 = blockIdx.y * 32;
    const int tx = threadIdx.x & 31, ty = threadIdx.x >> 5;
#pragma unroll
    for (int r = ty; r < 32; r += 8)
        tile[r][tx] = W[(size_t)(k0 + r) * Dsz + n0 + tx];
    __syncthreads();
#pragma unroll
    for (int r = ty; r < 32; r += 8) {
        float v = tile[tx][r];
        __nv_bfloat16 h = __float2bfloat16(v);
        __nv_bfloat16 l = __float2bfloat16(v - __bfloat162float(h));
        size_t o = (size_t)(n0 + r) * Dsz + k0 + tx;
        Th[o] = h;
        Tl[o] = l;
    }
}

// ============================================================
// bf16x3 GEMM via mma.sync (unchanged from R3)
// ============================================================
#define TILE_BYTES (128*80)
#define STAGE_BYTES (4*TILE_BYTES)
#define GEMM_SMEM (2*STAGE_BYTES)

__global__ __launch_bounds__(256, 1) void gemm_mma_bf16x3(
    const __nv_bfloat16* __restrict__ Ah, const __nv_bfloat16* __restrict__ Al,
    const __nv_bfloat16* __restrict__ Bh, const __nv_bfloat16* __restrict__ Bl,
    float* __restrict__ C)
{
    extern __shared__ char sm[];
    const int tid = threadIdx.x;
    const int wid = tid >> 5, lane = tid & 31;
    const int bx = blockIdx.x, by = blockIdx.y;
    const int wm = wid & 3;
    const int wn = wid >> 2;

    const uint32_t sbase = smem_to_u32(sm);

    const __nv_bfloat16* srcs[4] = {
        Ah + (size_t)(by * 128) * Dsz,
        Al + (size_t)(by * 128) * Dsz,
        Bh + (size_t)(bx * 128) * Dsz,
        Bl + (size_t)(bx * 128) * Dsz
    };

    float acc[2][8][4];
#pragma unroll
    for (int mt = 0; mt < 2; mt++)
#pragma unroll
        for (int nt = 0; nt < 8; nt++)
#pragma unroll
            for (int i = 0; i < 4; i++) acc[mt][nt][i] = 0.f;

    auto load_stage = [&](int kc) {
        const uint32_t sdst = sbase + (kc & 1) * STAGE_BYTES;
        const int k0 = kc * 32;
#pragma unroll
        for (int t = 0; t < 4; t++) {
            const __nv_bfloat16* src = srcs[t];
#pragma unroll
            for (int i = 0; i < 2; i++) {
                int id = i * 256 + tid;
                int r = id >> 2, c = id & 3;
                cp_async16(sdst + t * TILE_BYTES + r * 80 + c * 16,
                           src + (size_t)r * Dsz + k0 + c * 8);
            }
        }
        asm volatile("cp.async.commit_group;" ::: "memory");
    };

    load_stage(0);

    const int lrow = lane & 15;
    const int lcolb = (lane >> 4) * 16;

    for (int kc = 0; kc < 32; kc++) {
        if (kc < 31) load_stage(kc + 1);
        else asm volatile("cp.async.commit_group;" ::: "memory");
        asm volatile("cp.async.wait_group 1;" ::: "memory");
        __syncthreads();

        const uint32_t s = sbase + (kc & 1) * STAGE_BYTES;
        const uint32_t sAh = s;
        const uint32_t sAl = s + TILE_BYTES;
        const uint32_t sBh = s + 2 * TILE_BYTES;
        const uint32_t sBl = s + 3 * TILE_BYTES;

#pragma unroll
        for (int ks = 0; ks < 2; ks++) {
            const uint32_t cb = ks * 32 + lcolb;
            uint32_t ah[2][4], bh[4][4], al[2][4], bl[4][4];
#pragma unroll
            for (int mt = 0; mt < 2; mt++)
                ldsm4(ah[mt][0], ah[mt][1], ah[mt][2], ah[mt][3],
                      sAh + (wm * 32 + mt * 16 + lrow) * 80 + cb);
#pragma unroll
            for (int bt = 0; bt < 4; bt++)
                ldsm4(bh[bt][0], bh[bt][1], bh[bt][2], bh[bt][3],
                      sBh + (wn * 64 + bt * 16 + lrow) * 80 + cb);
#pragma unroll
            for (int mt = 0; mt < 2; mt++)
#pragma unroll
                for (int bt = 0; bt < 4; bt++) {
                    mma16816(acc[mt][bt*2],   ah[mt], bh[bt][0], bh[bt][2]);
                    mma16816(acc[mt][bt*2+1], ah[mt], bh[bt][1], bh[bt][3]);
                }
#pragma unroll
            for (int mt = 0; mt < 2; mt++)
                ldsm4(al[mt][0], al[mt][1], al[mt][2], al[mt][3],
                      sAl + (wm * 32 + mt * 16 + lrow) * 80 + cb);
#pragma unroll
            for (int mt = 0; mt < 2; mt++)
#pragma unroll
                for (int bt = 0; bt < 4; bt++) {
                    mma16816(acc[mt][bt*2],   al[mt], bh[bt][0], bh[bt][2]);
                    mma16816(acc[mt][bt*2+1], al[mt], bh[bt][1], bh[bt][3]);
                }
#pragma unroll
            for (int bt = 0; bt < 4; bt++)
                ldsm4(bl[bt][0], bl[bt][1], bl[bt][2], bl[bt][3],
                      sBl + (wn * 64 + bt * 16 + lrow) * 80 + cb);
#pragma unroll
            for (int mt = 0; mt < 2; mt++)
#pragma unroll
                for (int bt = 0; bt < 4; bt++) {
                    mma16816(acc[mt][bt*2],   ah[mt], bl[bt][0], bl[bt][2]);
                    mma16816(acc[mt][bt*2+1], ah[mt], bl[bt][1], bl[bt][3]);
                }
        }
        __syncthreads();
    }

    const int crow = by * 128 + wm * 32 + (lane >> 2);
    const int ccol = bx * 128 + wn * 64 + (lane & 3) * 2;
#pragma unroll
    for (int mt = 0; mt < 2; mt++) {
#pragma unroll
        for (int nt = 0; nt < 8; nt++) {
            float* p0 = C + (size_t)(crow + mt * 16) * Dsz + ccol + nt * 8;
            float* p1 = p0 + 8 * Dsz;
            *(float2*)p0 = make_float2(acc[mt][nt][0], acc[mt][nt][1]);
            *(float2*)p1 = make_float2(acc[mt][nt][2], acc[mt][nt][3]);
        }
    }
}

// ============================================================
// beta / dec projections (unchanged)
// ============================================================
__global__ __launch_bounds__(256) void beta_dec_kernel(
    const float* __restrict__ x, const float* __restrict__ Wb,
    const float* __restrict__ Wa, const float* __restrict__ A_log,
    const float* __restrict__ dt_bias,
    float* __restrict__ beta, float* __restrict__ dec)
{
    const int row = blockIdx.x * 8 + (threadIdx.x >> 5);
    const int lane = threadIdx.x & 31;
    if (row >= ROWS) return;

    float accb[4] = {0,0,0,0}, acca[4] = {0,0,0,0};
    const float* xr = x + (size_t)row * Dsz;
    const float4* Wb4 = (const float4*)Wb;
    const float4* Wa4 = (const float4*)Wa;

    for (int i = lane; i < Dsz; i += 32) {
        float xv = xr[i];
        float4 wb = Wb4[i];
        float4 wa = Wa4[i];
        accb[0] += xv * wb.x; accb[1] += xv * wb.y;
        accb[2] += xv * wb.z; accb[3] += xv * wb.w;
        acca[0] += xv * wa.x; acca[1] += xv * wa.y;
        acca[2] += xv * wa.z; acca[3] += xv * wa.w;
    }
#pragma unroll
    for (int off = 16; off; off >>= 1) {
#pragma unroll
        for (int h = 0; h < 4; h++) {
            accb[h] += __shfl_xor_sync(0xffffffffu, accb[h], off);
            acca[h] += __shfl_xor_sync(0xffffffffu, acca[h], off);
        }
    }
    if (lane < 4) {
        int h = lane;
        float bv = 1.f / (1.f + expf(-accb[h]));
        float a = acca[h] + dt_bias[h];
        float sp = fmaxf(a, 0.f) + log1pf(expf(-fabsf(a)));
        float dv = expf(-expf(A_log[h]) * sp);
        beta[(size_t)row * Hsz + h] = bv;
        dec [(size_t)row * Hsz + h] = dv;
    }
}

// ============================================================
// L2-normalize q and k (unchanged)
// ============================================================
__global__ __launch_bounds__(256) void norm_qk_kernel(float* __restrict__ q,
                                                      float* __restrict__ k)
{
    const int row = blockIdx.x * 8 + (threadIdx.x >> 5);
    const int lane = threadIdx.x & 31;
    float4* qr = (float4*)(q + (size_t)row * DKsz);
    float4* kr = (float4*)(k + (size_t)row * DKsz);
    float4 q0 = qr[lane * 2], q1 = qr[lane * 2 + 1];
    float4 k0 = kr[lane * 2], k1 = kr[lane * 2 + 1];

    float sq = q0.x*q0.x + q0.y*q0.y + q0.z*q0.z + q0.w*q0.w
             + q1.x*q1.x + q1.y*q1.y + q1.z*q1.z + q1.w*q1.w;
    float sk = k0.x*k0.x + k0.y*k0.y + k0.z*k0.z + k0.w*k0.w
             + k1.x*k1.x + k1.y*k1.y + k1.z*k1.z + k1.w*k1.w;
#pragma unroll
    for (int off = 16; off; off >>= 1) {
        sq += __shfl_xor_sync(0xffffffffu, sq, off);
        sk += __shfl_xor_sync(0xffffffffu, sk, off);
    }
    float qs = rsqrtf(sq + 1e-6f) * 0.0625f;
    float ks = rsqrtf(sk + 1e-6f);
    q0.x*=qs; q0.y*=qs; q0.z*=qs; q0.w*=qs;
    q1.x*=qs; q1.y*=qs; q1.z*=qs; q1.w*=qs;
    k0.x*=ks; k0.y*=ks; k0.z*=ks; k0.w*=ks;
    k1.x*=ks; k1.y*=ks; k1.z*=ks; k1.w*=ks;
    qr[lane * 2] = q0; qr[lane * 2 + 1] = q1;
    kr[lane * 2] = k0; kr[lane * 2 + 1] = k1;
}

// ============================================================
// Gated delta-rule recurrence — R3 algorithm, f32x2-packed math,
// contiguous-row state layout (lane owns rows lane*4..+3 and
// 128+lane*4..+3) so k/q tile reads are 4 conflict-free LDS.128.
// ============================================================
__global__ __launch_bounds__(256) void recurrence_kernel(
    const float* __restrict__ q, const float* __restrict__ k,
    const float* __restrict__ v, const float* __restrict__ beta,
    const float* __restrict__ dec, float* __restrict__ o)
{
    const int cta = blockIdx.x;       // 512
    const int bh = cta >> 5;          // 0..15
    const int jg = cta & 31;          // column group
    const int b = bh >> 2, h = bh & 3;
    const int w = threadIdx.x >> 5, lane = threadIdx.x & 31;
    const int j = jg * 8 + w;

    __shared__ float sk[STEPS][DKsz];
    __shared__ float sq[STEPS][DKsz];
    __shared__ float sv[STEPS][8];
    __shared__ float sb[STEPS], sd[STEPS];

    // state: rows lane*4..+3 in s2[0..1], rows 128+lane*4..+3 in s2[2..3]
    u64t s2[4] = {0ull, 0ull, 0ull, 0ull};

    const size_t rowbase = (size_t)b * Tsz * Dsz + h * DKsz;
    const int ro0 = lane * 4;           // first row block (float index)
    const int ro1 = 128 + lane * 4;     // second row block

    for (int t0 = 0; t0 < Tsz; t0 += STEPS) {
        __syncthreads();
        // cooperative load of k/q tiles: 16 steps x 256 floats each
#pragma unroll
        for (int r = 0; r < 4; r++) {
            int idx = r * 256 + threadIdx.x;
            int ss = idx >> 6;
            int d4 = (idx & 63) * 4;
            size_t gaddr = rowbase + (size_t)(t0 + ss) * Dsz + d4;
            *(float4*)&sk[ss][d4] = *(const float4*)(k + gaddr);
            *(float4*)&sq[ss][d4] = *(const float4*)(q + gaddr);
        }
        if (threadIdx.x < 128) {
            int ss = threadIdx.x >> 3, jj = threadIdx.x & 7;
            sv[ss][jj] = v[rowbase + (size_t)(t0 + ss) * Dsz + jg * 8 + jj];
        }
        if (threadIdx.x < STEPS) {
            size_t bidx = (size_t)(b * Tsz + t0 + threadIdx.x) * Hsz + h;
            sb[threadIdx.x] = beta[bidx];
            sd[threadIdx.x] = dec[bidx];
        }
        __syncthreads();

#pragma unroll 4
        for (int ss = 0; ss < STEPS; ss++) {
            const float de = sd[ss], be = sb[ss], vj = sv[ss][w];
            // k slices (2x LDS.128, conflict-free)
            const ulonglong2 ka = *(const ulonglong2*)&sk[ss][ro0];
            const ulonglong2 kb = *(const ulonglong2*)&sk[ss][ro1];
            // p_partial = k . s   (packed; decay folded in after reduce)
            u64t a0, a1;
            mul2(a0, ka.x, s2[0]); fma2(a0, ka.y, s2[1], a0);
            mul2(a1, kb.x, s2[2]); fma2(a1, kb.y, s2[3], a1);
            add2(a0, a0, a1);
            float p = sum2(a0);
#pragma unroll
            for (int off = 16; off; off >>= 1)
                p += __shfl_xor_sync(0xffffffffu, p, off);
            // u = beta * (v - de * (k . S_old))   [S decayed by de]
            const float u = be * fmaf(-de, p, vj);
            const u64t dd = pack2(de);
            const u64t uu = pack2(u);
            // s = de*s + k*u
            mul2(s2[0], s2[0], dd); fma2(s2[0], ka.x, uu, s2[0]);
            mul2(s2[1], s2[1], dd); fma2(s2[1], ka.y, uu, s2[1]);
            mul2(s2[2], s2[2], dd); fma2(s2[2], kb.x, uu, s2[2]);
            mul2(s2[3], s2[3], dd); fma2(s2[3], kb.y, uu, s2[3]);
            // o = q . s
            const ulonglong2 qa = *(const ulonglong2*)&sq[ss][ro0];
            const ulonglong2 qb = *(const ulonglong2*)&sq[ss][ro1];
            u64t b0, b1;
            mul2(b0, qa.x, s2[0]); fma2(b0, qa.y, s2[1], b0);
            mul2(b1, qb.x, s2[2]); fma2(b1, qb.y, s2[3], b1);
            add2(b0, b0, b1);
            float ov = sum2(b0);
#pragma unroll
            for (int off = 16; off; off >>= 1)
                ov += __shfl_xor_sync(0xffffffffu, ov, off);
            if (lane == 0)
                o[rowbase + (size_t)(t0 + ss) * Dsz + j] = ov;
        }
    }
}

// ============================================================
// Gated RMSNorm (unchanged)
// ============================================================
__global__ __launch_bounds__(256) void gate_norm_kernel(
    const float* __restrict__ o, const float* __restrict__ g,
    const float* __restrict__ norm_w, float* __restrict__ out)
{
    const int row = blockIdx.x * 8 + (threadIdx.x >> 5);
    const int lane = threadIdx.x & 31;
    const float4* orow = (const float4*)(o + (size_t)row * DVsz);
    float4 o0 = orow[lane * 2], o1 = orow[lane * 2 + 1];

    float ss = o0.x*o0.x + o0.y*o0.y + o0.z*o0.z + o0.w*o0.w
             + o1.x*o1.x + o1.y*o1.y + o1.z*o1.z + o1.w*o1.w;
#pragma unroll
    for (int off = 16; off; off >>= 1)
        ss += __shfl_xor_sync(0xffffffffu, ss, off);
    float r = rsqrtf(ss * (1.f / 256.f) + 1e-5f);

    const float4* nw = (const float4*)norm_w;
    float4 w0 = nw[lane * 2], w1 = nw[lane * 2 + 1];
    const float4* grow = (const float4*)(g + (size_t)row * DVsz);
    float4 g0 = grow[lane * 2], g1 = grow[lane * 2 + 1];

    float4 r0, r1;
    r0.x = o0.x * r * w0.x * (g0.x / (1.f + expf(-g0.x)));
    r0.y = o0.y * r * w0.y * (g0.y / (1.f + expf(-g0.y)));
    r0.z = o0.z * r * w0.z * (g0.z / (1.f + expf(-g0.z)));
    r0.w = o0.w * r * w0.w * (g0.w / (1.f + expf(-g0.w)));
    r1.x = o1.x * r * w1.x * (g1.x / (1.f + expf(-g1.x)));
    r1.y = o1.y * r * w1.y * (g1.y / (1.f + expf(-g1.y)));
    r1.z = o1.z * r * w1.z * (g1.z / (1.f + expf(-g1.z)));
    r1.w = o1.w * r * w1.w * (g1.w / (1.f + expf(-g1.w)));

    float4* outr = (float4*)(out + (size_t)row * DVsz);
    outr[lane * 2] = r0;
    outr[lane * 2 + 1] = r1;
}

// ============================================================
// host launch
// ============================================================
extern "C" void kernel_launch(void* const* d_in, const int* in_sizes, int n_in,
                              void* d_out, int out_size)
{
    const float* x       = (const float*)d_in[0];
    const float* Wq      = (const float*)d_in[1];
    const float* Wk      = (const float*)d_in[2];
    const float* Wv      = (const float*)d_in[3];
    const float* Wb      = (const float*)d_in[4];
    const float* Wa      = (const float*)d_in[5];
    const float* A_log   = (const float*)d_in[6];
    const float* dt_bias = (const float*)d_in[7];
    const float* Wg      = (const float*)d_in[8];
    const float* norm_w  = (const float*)d_in[9];
    const float* Wo      = (const float*)d_in[10];
    float* out = (float*)d_out;

    float *q, *k, *v, *g, *o, *beta, *dec;
    cudaGetSymbolAddress((void**)&q, g_q);
    cudaGetSymbolAddress((void**)&k, g_k);
    cudaGetSymbolAddress((void**)&v, g_v);
    cudaGetSymbolAddress((void**)&g, g_g);
    cudaGetSymbolAddress((void**)&o, g_o);
    cudaGetSymbolAddress((void**)&beta, g_beta);
    cudaGetSymbolAddress((void**)&dec, g_dec);
    __nv_bfloat16 *xh, *xl, *yh, *yl, *wth, *wtl;
    cudaGetSymbolAddress((void**)&xh, g_xh);
    cudaGetSymbolAddress((void**)&xl, g_xl);
    cudaGetSymbolAddress((void**)&yh, g_yh);
    cudaGetSymbolAddress((void**)&yl, g_yl);
    cudaGetSymbolAddress((void**)&wth, g_wth);
    cudaGetSymbolAddress((void**)&wtl, g_wtl);

    cudaFuncSetAttribute(gemm_mma_bf16x3,
                         cudaFuncAttributeMaxDynamicSharedMemorySize,
                         GEMM_SMEM);

    dim3 tgrid(Dsz / 32, Dsz / 32);
    transpose_split_kernel<<<tgrid, 256>>>(Wq, wth + 0*Dsz*Dsz, wtl + 0*Dsz*Dsz);
    transpose_split_kernel<<<tgrid, 256>>>(Wk, wth + 1*Dsz*Dsz, wtl + 1*Dsz*Dsz);
    transpose_split_kernel<<<tgrid, 256>>>(Wv, wth + 2*Dsz*Dsz, wtl + 2*Dsz*Dsz);
    transpose_split_kernel<<<tgrid, 256>>>(Wg, wth + 3*Dsz*Dsz, wtl + 3*Dsz*Dsz);
    transpose_split_kernel<<<tgrid, 256>>>(Wo, wth + 4*Dsz*Dsz, wtl + 4*Dsz*Dsz);
    split_kernel<<<(ROWS * Dsz / 4) / 256, 256>>>(x, xh, xl);

    dim3 ggrid(Dsz / 128, ROWS / 128);
    gemm_mma_bf16x3<<<ggrid, 256, GEMM_SMEM>>>(xh, xl, wth + 0*Dsz*Dsz, wtl + 0*Dsz*Dsz, q);
    gemm_mma_bf16x3<<<ggrid, 256, GEMM_SMEM>>>(xh, xl, wth + 1*Dsz*Dsz, wtl + 1*Dsz*Dsz, k);
    gemm_mma_bf16x3<<<ggrid, 256, GEMM_SMEM>>>(xh, xl, wth + 2*Dsz*Dsz, wtl + 2*Dsz*Dsz, v);
    gemm_mma_bf16x3<<<ggrid, 256, GEMM_SMEM>>>(xh, xl, wth + 3*Dsz*Dsz, wtl + 3*Dsz*Dsz, g);

    beta_dec_kernel<<<ROWS / 8, 256>>>(x, Wb, Wa, A_log, dt_bias, beta, dec);
    norm_qk_kernel<<<(ROWS * Hsz) / 8, 256>>>(q, k);

    recurrence_kernel<<<Bsz * Hsz * 32, 256>>>(q, k, v, beta, dec, o);

    gate_norm_kernel<<<(ROWS * Hsz) / 8, 256>>>(o, g, norm_w, q);
    split_kernel<<<(ROWS * Dsz / 4) / 256, 256>>>(q, yh, yl);
    gemm_mma_bf16x3<<<ggrid, 256, GEMM_SMEM>>>(yh, yl, wth + 4*Dsz*Dsz, wtl + 4*Dsz*Dsz, out);
}

// round 6
// speedup vs baseline: 1.6445x; 1.0015x over previous
#include <cuda_runtime.h>
#include <cuda_bf16.h>
#include <math.h>
#include <cstdint>

// Problem constants
#define Bsz 4
#define Tsz 4096
#define Dsz 1024
#define Hsz 4
#define DKsz 256
#define DVsz 256
#define ROWS (Bsz*Tsz)        // 16384
#define STEPS 16

// -------- static device scratch (no allocations allowed) --------
__device__ float g_q[ROWS * Dsz];
__device__ float g_k[ROWS * Dsz];
__device__ float g_v[ROWS * Dsz];
__device__ float g_g[ROWS * Dsz];
__device__ float g_o[ROWS * Dsz];
__device__ float g_beta[ROWS * Hsz];
__device__ float g_dec[ROWS * Hsz];
// bf16 split operands
__device__ __nv_bfloat16 g_xh[ROWS * Dsz];
__device__ __nv_bfloat16 g_xl[ROWS * Dsz];
__device__ __nv_bfloat16 g_yh[ROWS * Dsz];
__device__ __nv_bfloat16 g_yl[ROWS * Dsz];
__device__ __nv_bfloat16 g_wth[5 * Dsz * Dsz];
__device__ __nv_bfloat16 g_wtl[5 * Dsz * Dsz];

// ============================================================
// helpers (baseline PTX only)
// ============================================================
__device__ __forceinline__ uint32_t smem_to_u32(const void* p) {
    uint32_t a;
    asm("{ .reg .u64 t; cvta.to.shared.u64 t, %1; cvt.u32.u64 %0, t; }"
        : "=r"(a) : "l"(p));
    return a;
}
__device__ __forceinline__ void cp_async16(uint32_t s, const void* g) {
    asm volatile("cp.async.cg.shared.global [%0], [%1], 16;" :: "r"(s), "l"(g));
}
__device__ __forceinline__ void ldsm4(uint32_t& r0, uint32_t& r1, uint32_t& r2,
                                      uint32_t& r3, uint32_t addr) {
    asm volatile("ldmatrix.sync.aligned.m8n8.x4.shared.b16 {%0,%1,%2,%3}, [%4];"
                 : "=r"(r0), "=r"(r1), "=r"(r2), "=r"(r3) : "r"(addr));
}
__device__ __forceinline__ void mma16816(float* c, const uint32_t* a,
                                         uint32_t b0, uint32_t b1) {
    asm volatile(
        "mma.sync.aligned.m16n8k16.row.col.f32.bf16.bf16.f32 "
        "{%0,%1,%2,%3}, {%4,%5,%6,%7}, {%8,%9}, {%0,%1,%2,%3};"
        : "+f"(c[0]), "+f"(c[1]), "+f"(c[2]), "+f"(c[3])
        : "r"(a[0]), "r"(a[1]), "r"(a[2]), "r"(a[3]), "r"(b0), "r"(b1));
}
// ---- packed f32x2 (sm_100+ base ISA) ----
typedef unsigned long long u64t;
__device__ __forceinline__ u64t pack2(float x) {
    u64t r;
    asm("mov.b64 %0, {%1, %1};" : "=l"(r) : "f"(x));
    return r;
}
__device__ __forceinline__ void fma2(u64t& d, u64t a, u64t b, u64t c) {
    asm("fma.rn.f32x2 %0, %1, %2, %3;" : "=l"(d) : "l"(a), "l"(b), "l"(c));
}
__device__ __forceinline__ void mul2(u64t& d, u64t a, u64t b) {
    asm("mul.rn.f32x2 %0, %1, %2;" : "=l"(d) : "l"(a), "l"(b));
}
__device__ __forceinline__ void add2(u64t& d, u64t a, u64t b) {
    asm("add.rn.f32x2 %0, %1, %2;" : "=l"(d) : "l"(a), "l"(b));
}
__device__ __forceinline__ float sum2(u64t a) {
    float lo, hi;
    asm("mov.b64 {%0, %1}, %2;" : "=f"(lo), "=f"(hi) : "l"(a));
    return lo + hi;
}

// ============================================================
// fp32 -> (hi, lo) bf16 split
// ============================================================
__global__ __launch_bounds__(256) void split_kernel(
    const float* __restrict__ src, __nv_bfloat16* __restrict__ hi,
    __nv_bfloat16* __restrict__ lo)
{
    const int i = blockIdx.x * 256 + threadIdx.x;
    float4 v = ((const float4*)src)[i];
    __nv_bfloat16 h0 = __float2bfloat16(v.x), h1 = __float2bfloat16(v.y);
    __nv_bfloat16 h2 = __float2bfloat16(v.z), h3 = __float2bfloat16(v.w);
    __nv_bfloat16 l0 = __float2bfloat16(v.x - __bfloat162float(h0));
    __nv_bfloat16 l1 = __float2bfloat16(v.y - __bfloat162float(h1));
    __nv_bfloat16 l2 = __float2bfloat16(v.z - __bfloat162float(h2));
    __nv_bfloat16 l3 = __float2bfloat16(v.w - __bfloat162float(h3));
    ((__nv_bfloat162*)hi)[i*2]   = __halves2bfloat162(h0, h1);
    ((__nv_bfloat162*)hi)[i*2+1] = __halves2bfloat162(h2, h3);
    ((__nv_bfloat162*)lo)[i*2]   = __halves2bfloat162(l0, l1);
    ((__nv_bfloat162*)lo)[i*2+1] = __halves2bfloat162(l2, l3);
}

// ============================================================
// transpose 1024x1024 fp32 weight, split into hi/lo bf16
// ============================================================
__global__ __launch_bounds__(256) void transpose_split_kernel(
    const float* __restrict__ W, __nv_bfloat16* __restrict__ Th,
    __nv_bfloat16* __restrict__ Tl)
{
    __shared__ float tile[32][33];
    const int n0 = blockIdx.x * 32, k0 = blockIdx.y * 32;
    const int tx = threadIdx.x & 31, ty = threadIdx.x >> 5;
#pragma unroll
    for (int r = ty; r < 32; r += 8)
        tile[r][tx] = W[(size_t)(k0 + r) * Dsz + n0 + tx];
    __syncthreads();
#pragma unroll
    for (int r = ty; r < 32; r += 8) {
        float v = tile[tx][r];
        __nv_bfloat16 h = __float2bfloat16(v);
        __nv_bfloat16 l = __float2bfloat16(v - __bfloat162float(h));
        size_t o = (size_t)(n0 + r) * Dsz + k0 + tx;
        Th[o] = h;
        Tl[o] = l;
    }
}

// ============================================================
// bf16x3 GEMM via mma.sync (unchanged from R3)
// ============================================================
#define TILE_BYTES (128*80)
#define STAGE_BYTES (4*TILE_BYTES)
#define GEMM_SMEM (2*STAGE_BYTES)

__global__ __launch_bounds__(256, 1) void gemm_mma_bf16x3(
    const __nv_bfloat16* __restrict__ Ah, const __nv_bfloat16* __restrict__ Al,
    const __nv_bfloat16* __restrict__ Bh, const __nv_bfloat16* __restrict__ Bl,
    float* __restrict__ C)
{
    extern __shared__ char sm[];
    const int tid = threadIdx.x;
    const int wid = tid >> 5, lane = tid & 31;
    const int bx = blockIdx.x, by = blockIdx.y;
    const int wm = wid & 3;
    const int wn = wid >> 2;

    const uint32_t sbase = smem_to_u32(sm);

    const __nv_bfloat16* srcs[4] = {
        Ah + (size_t)(by * 128) * Dsz,
        Al + (size_t)(by * 128) * Dsz,
        Bh + (size_t)(bx * 128) * Dsz,
        Bl + (size_t)(bx * 128) * Dsz
    };

    float acc[2][8][4];
#pragma unroll
    for (int mt = 0; mt < 2; mt++)
#pragma unroll
        for (int nt = 0; nt < 8; nt++)
#pragma unroll
            for (int i = 0; i < 4; i++) acc[mt][nt][i] = 0.f;

    auto load_stage = [&](int kc) {
        const uint32_t sdst = sbase + (kc & 1) * STAGE_BYTES;
        const int k0 = kc * 32;
#pragma unroll
        for (int t = 0; t < 4; t++) {
            const __nv_bfloat16* src = srcs[t];
#pragma unroll
            for (int i = 0; i < 2; i++) {
                int id = i * 256 + tid;
                int r = id >> 2, c = id & 3;
                cp_async16(sdst + t * TILE_BYTES + r * 80 + c * 16,
                           src + (size_t)r * Dsz + k0 + c * 8);
            }
        }
        asm volatile("cp.async.commit_group;" ::: "memory");
    };

    load_stage(0);

    const int lrow = lane & 15;
    const int lcolb = (lane >> 4) * 16;

    for (int kc = 0; kc < 32; kc++) {
        if (kc < 31) load_stage(kc + 1);
        else asm volatile("cp.async.commit_group;" ::: "memory");
        asm volatile("cp.async.wait_group 1;" ::: "memory");
        __syncthreads();

        const uint32_t s = sbase + (kc & 1) * STAGE_BYTES;
        const uint32_t sAh = s;
        const uint32_t sAl = s + TILE_BYTES;
        const uint32_t sBh = s + 2 * TILE_BYTES;
        const uint32_t sBl = s + 3 * TILE_BYTES;

#pragma unroll
        for (int ks = 0; ks < 2; ks++) {
            const uint32_t cb = ks * 32 + lcolb;
            uint32_t ah[2][4], bh[4][4], al[2][4], bl[4][4];
#pragma unroll
            for (int mt = 0; mt < 2; mt++)
                ldsm4(ah[mt][0], ah[mt][1], ah[mt][2], ah[mt][3],
                      sAh + (wm * 32 + mt * 16 + lrow) * 80 + cb);
#pragma unroll
            for (int bt = 0; bt < 4; bt++)
                ldsm4(bh[bt][0], bh[bt][1], bh[bt][2], bh[bt][3],
                      sBh + (wn * 64 + bt * 16 + lrow) * 80 + cb);
#pragma unroll
            for (int mt = 0; mt < 2; mt++)
#pragma unroll
                for (int bt = 0; bt < 4; bt++) {
                    mma16816(acc[mt][bt*2],   ah[mt], bh[bt][0], bh[bt][2]);
                    mma16816(acc[mt][bt*2+1], ah[mt], bh[bt][1], bh[bt][3]);
                }
#pragma unroll
            for (int mt = 0; mt < 2; mt++)
                ldsm4(al[mt][0], al[mt][1], al[mt][2], al[mt][3],
                      sAl + (wm * 32 + mt * 16 + lrow) * 80 + cb);
#pragma unroll
            for (int mt = 0; mt < 2; mt++)
#pragma unroll
                for (int bt = 0; bt < 4; bt++) {
                    mma16816(acc[mt][bt*2],   al[mt], bh[bt][0], bh[bt][2]);
                    mma16816(acc[mt][bt*2+1], al[mt], bh[bt][1], bh[bt][3]);
                }
#pragma unroll
            for (int bt = 0; bt < 4; bt++)
                ldsm4(bl[bt][0], bl[bt][1], bl[bt][2], bl[bt][3],
                      sBl + (wn * 64 + bt * 16 + lrow) * 80 + cb);
#pragma unroll
            for (int mt = 0; mt < 2; mt++)
#pragma unroll
                for (int bt = 0; bt < 4; bt++) {
                    mma16816(acc[mt][bt*2],   ah[mt], bl[bt][0], bl[bt][2]);
                    mma16816(acc[mt][bt*2+1], ah[mt], bl[bt][1], bl[bt][3]);
                }
        }
        __syncthreads();
    }

    const int crow = by * 128 + wm * 32 + (lane >> 2);
    const int ccol = bx * 128 + wn * 64 + (lane & 3) * 2;
#pragma unroll
    for (int mt = 0; mt < 2; mt++) {
#pragma unroll
        for (int nt = 0; nt < 8; nt++) {
            float* p0 = C + (size_t)(crow + mt * 16) * Dsz + ccol + nt * 8;
            float* p1 = p0 + 8 * Dsz;
            *(float2*)p0 = make_float2(acc[mt][nt][0], acc[mt][nt][1]);
            *(float2*)p1 = make_float2(acc[mt][nt][2], acc[mt][nt][3]);
        }
    }
}

// ============================================================
// beta / dec projections (unchanged)
// ============================================================
__global__ __launch_bounds__(256) void beta_dec_kernel(
    const float* __restrict__ x, const float* __restrict__ Wb,
    const float* __restrict__ Wa, const float* __restrict__ A_log,
    const float* __restrict__ dt_bias,
    float* __restrict__ beta, float* __restrict__ dec)
{
    const int row = blockIdx.x * 8 + (threadIdx.x >> 5);
    const int lane = threadIdx.x & 31;
    if (row >= ROWS) return;

    float accb[4] = {0,0,0,0}, acca[4] = {0,0,0,0};
    const float* xr = x + (size_t)row * Dsz;
    const float4* Wb4 = (const float4*)Wb;
    const float4* Wa4 = (const float4*)Wa;

    for (int i = lane; i < Dsz; i += 32) {
        float xv = xr[i];
        float4 wb = Wb4[i];
        float4 wa = Wa4[i];
        accb[0] += xv * wb.x; accb[1] += xv * wb.y;
        accb[2] += xv * wb.z; accb[3] += xv * wb.w;
        acca[0] += xv * wa.x; acca[1] += xv * wa.y;
        acca[2] += xv * wa.z; acca[3] += xv * wa.w;
    }
#pragma unroll
    for (int off = 16; off; off >>= 1) {
#pragma unroll
        for (int h = 0; h < 4; h++) {
            accb[h] += __shfl_xor_sync(0xffffffffu, accb[h], off);
            acca[h] += __shfl_xor_sync(0xffffffffu, acca[h], off);
        }
    }
    if (lane < 4) {
        int h = lane;
        float bv = 1.f / (1.f + expf(-accb[h]));
        float a = acca[h] + dt_bias[h];
        float sp = fmaxf(a, 0.f) + log1pf(expf(-fabsf(a)));
        float dv = expf(-expf(A_log[h]) * sp);
        beta[(size_t)row * Hsz + h] = bv;
        dec [(size_t)row * Hsz + h] = dv;
    }
}

// ============================================================
// L2-normalize q and k (unchanged)
// ============================================================
__global__ __launch_bounds__(256) void norm_qk_kernel(float* __restrict__ q,
                                                      float* __restrict__ k)
{
    const int row = blockIdx.x * 8 + (threadIdx.x >> 5);
    const int lane = threadIdx.x & 31;
    float4* qr = (float4*)(q + (size_t)row * DKsz);
    float4* kr = (float4*)(k + (size_t)row * DKsz);
    float4 q0 = qr[lane * 2], q1 = qr[lane * 2 + 1];
    float4 k0 = kr[lane * 2], k1 = kr[lane * 2 + 1];

    float sq = q0.x*q0.x + q0.y*q0.y + q0.z*q0.z + q0.w*q0.w
             + q1.x*q1.x + q1.y*q1.y + q1.z*q1.z + q1.w*q1.w;
    float sk = k0.x*k0.x + k0.y*k0.y + k0.z*k0.z + k0.w*k0.w
             + k1.x*k1.x + k1.y*k1.y + k1.z*k1.z + k1.w*k1.w;
#pragma unroll
    for (int off = 16; off; off >>= 1) {
        sq += __shfl_xor_sync(0xffffffffu, sq, off);
        sk += __shfl_xor_sync(0xffffffffu, sk, off);
    }
    float qs = rsqrtf(sq + 1e-6f) * 0.0625f;
    float ks = rsqrtf(sk + 1e-6f);
    q0.x*=qs; q0.y*=qs; q0.z*=qs; q0.w*=qs;
    q1.x*=qs; q1.y*=qs; q1.z*=qs; q1.w*=qs;
    k0.x*=ks; k0.y*=ks; k0.z*=ks; k0.w*=ks;
    k1.x*=ks; k1.y*=ks; k1.z*=ks; k1.w*=ks;
    qr[lane * 2] = q0; qr[lane * 2 + 1] = q1;
    kr[lane * 2] = k0; kr[lane * 2 + 1] = k1;
}

// ============================================================
// Gated delta-rule recurrence — R3 algorithm, f32x2-packed math,
// contiguous-row state layout (lane owns rows lane*4..+3 and
// 128+lane*4..+3) so k/q tile reads are 4 conflict-free LDS.128.
// ============================================================
__global__ __launch_bounds__(256) void recurrence_kernel(
    const float* __restrict__ q, const float* __restrict__ k,
    const float* __restrict__ v, const float* __restrict__ beta,
    const float* __restrict__ dec, float* __restrict__ o)
{
    const int cta = blockIdx.x;       // 512
    const int bh = cta >> 5;          // 0..15
    const int jg = cta & 31;          // column group
    const int b = bh >> 2, h = bh & 3;
    const int w = threadIdx.x >> 5, lane = threadIdx.x & 31;
    const int j = jg * 8 + w;

    __shared__ float sk[STEPS][DKsz];
    __shared__ float sq[STEPS][DKsz];
    __shared__ float sv[STEPS][8];
    __shared__ float sb[STEPS], sd[STEPS];

    // state: rows lane*4..+3 in s2[0..1], rows 128+lane*4..+3 in s2[2..3]
    u64t s2[4] = {0ull, 0ull, 0ull, 0ull};

    const size_t rowbase = (size_t)b * Tsz * Dsz + h * DKsz;
    const int ro0 = lane * 4;           // first row block (float index)
    const int ro1 = 128 + lane * 4;     // second row block

    for (int t0 = 0; t0 < Tsz; t0 += STEPS) {
        __syncthreads();
        // cooperative load of k/q tiles: 16 steps x 256 floats each
#pragma unroll
        for (int r = 0; r < 4; r++) {
            int idx = r * 256 + threadIdx.x;
            int ss = idx >> 6;
            int d4 = (idx & 63) * 4;
            size_t gaddr = rowbase + (size_t)(t0 + ss) * Dsz + d4;
            *(float4*)&sk[ss][d4] = *(const float4*)(k + gaddr);
            *(float4*)&sq[ss][d4] = *(const float4*)(q + gaddr);
        }
        if (threadIdx.x < 128) {
            int ss = threadIdx.x >> 3, jj = threadIdx.x & 7;
            sv[ss][jj] = v[rowbase + (size_t)(t0 + ss) * Dsz + jg * 8 + jj];
        }
        if (threadIdx.x < STEPS) {
            size_t bidx = (size_t)(b * Tsz + t0 + threadIdx.x) * Hsz + h;
            sb[threadIdx.x] = beta[bidx];
            sd[threadIdx.x] = dec[bidx];
        }
        __syncthreads();

#pragma unroll 4
        for (int ss = 0; ss < STEPS; ss++) {
            const float de = sd[ss], be = sb[ss], vj = sv[ss][w];
            // k slices (2x LDS.128, conflict-free)
            const ulonglong2 ka = *(const ulonglong2*)&sk[ss][ro0];
            const ulonglong2 kb = *(const ulonglong2*)&sk[ss][ro1];
            // p_partial = k . s   (packed; decay folded in after reduce)
            u64t a0, a1;
            mul2(a0, ka.x, s2[0]); fma2(a0, ka.y, s2[1], a0);
            mul2(a1, kb.x, s2[2]); fma2(a1, kb.y, s2[3], a1);
            add2(a0, a0, a1);
            float p = sum2(a0);
#pragma unroll
            for (int off = 16; off; off >>= 1)
                p += __shfl_xor_sync(0xffffffffu, p, off);
            // u = beta * (v - de * (k . S_old))   [S decayed by de]
            const float u = be * fmaf(-de, p, vj);
            const u64t dd = pack2(de);
            const u64t uu = pack2(u);
            // s = de*s + k*u
            mul2(s2[0], s2[0], dd); fma2(s2[0], ka.x, uu, s2[0]);
            mul2(s2[1], s2[1], dd); fma2(s2[1], ka.y, uu, s2[1]);
            mul2(s2[2], s2[2], dd); fma2(s2[2], kb.x, uu, s2[2]);
            mul2(s2[3], s2[3], dd); fma2(s2[3], kb.y, uu, s2[3]);
            // o = q . s
            const ulonglong2 qa = *(const ulonglong2*)&sq[ss][ro0];
            const ulonglong2 qb = *(const ulonglong2*)&sq[ss][ro1];
            u64t b0, b1;
            mul2(b0, qa.x, s2[0]); fma2(b0, qa.y, s2[1], b0);
            mul2(b1, qb.x, s2[2]); fma2(b1, qb.y, s2[3], b1);
            add2(b0, b0, b1);
            float ov = sum2(b0);
#pragma unroll
            for (int off = 16; off; off >>= 1)
                ov += __shfl_xor_sync(0xffffffffu, ov, off);
            if (lane == 0)
                o[rowbase + (size_t)(t0 + ss) * Dsz + j] = ov;
        }
    }
}

// ============================================================
// Gated RMSNorm (unchanged)
// ============================================================
__global__ __launch_bounds__(256) void gate_norm_kernel(
    const float* __restrict__ o, const float* __restrict__ g,
    const float* __restrict__ norm_w, float* __restrict__ out)
{
    const int row = blockIdx.x * 8 + (threadIdx.x >> 5);
    const int lane = threadIdx.x & 31;
    const float4* orow = (const float4*)(o + (size_t)row * DVsz);
    float4 o0 = orow[lane * 2], o1 = orow[lane * 2 + 1];

    float ss = o0.x*o0.x + o0.y*o0.y + o0.z*o0.z + o0.w*o0.w
             + o1.x*o1.x + o1.y*o1.y + o1.z*o1.z + o1.w*o1.w;
#pragma unroll
    for (int off = 16; off; off >>= 1)
        ss += __shfl_xor_sync(0xffffffffu, ss, off);
    float r = rsqrtf(ss * (1.f / 256.f) + 1e-5f);

    const float4* nw = (const float4*)norm_w;
    float4 w0 = nw[lane * 2], w1 = nw[lane * 2 + 1];
    const float4* grow = (const float4*)(g + (size_t)row * DVsz);
    float4 g0 = grow[lane * 2], g1 = grow[lane * 2 + 1];

    float4 r0, r1;
    r0.x = o0.x * r * w0.x * (g0.x / (1.f + expf(-g0.x)));
    r0.y = o0.y * r * w0.y * (g0.y / (1.f + expf(-g0.y)));
    r0.z = o0.z * r * w0.z * (g0.z / (1.f + expf(-g0.z)));
    r0.w = o0.w * r * w0.w * (g0.w / (1.f + expf(-g0.w)));
    r1.x = o1.x * r * w1.x * (g1.x / (1.f + expf(-g1.x)));
    r1.y = o1.y * r * w1.y * (g1.y / (1.f + expf(-g1.y)));
    r1.z = o1.z * r * w1.z * (g1.z / (1.f + expf(-g1.z)));
    r1.w = o1.w * r * w1.w * (g1.w / (1.f + expf(-g1.w)));

    float4* outr = (float4*)(out + (size_t)row * DVsz);
    outr[lane * 2] = r0;
    outr[lane * 2 + 1] = r1;
}

// ============================================================
// host launch
// ============================================================
extern "C" void kernel_launch(void* const* d_in, const int* in_sizes, int n_in,
                              void* d_out, int out_size)
{
    const float* x       = (const float*)d_in[0];
    const float* Wq      = (const float*)d_in[1];
    const float* Wk      = (const float*)d_in[2];
    const float* Wv      = (const float*)d_in[3];
    const float* Wb      = (const float*)d_in[4];
    const float* Wa      = (const float*)d_in[5];
    const float* A_log   = (const float*)d_in[6];
    const float* dt_bias = (const float*)d_in[7];
    const float* Wg      = (const float*)d_in[8];
    const float* norm_w  = (const float*)d_in[9];
    const float* Wo      = (const float*)d_in[10];
    float* out = (float*)d_out;

    float *q, *k, *v, *g, *o, *beta, *dec;
    cudaGetSymbolAddress((void**)&q, g_q);
    cudaGetSymbolAddress((void**)&k, g_k);
    cudaGetSymbolAddress((void**)&v, g_v);
    cudaGetSymbolAddress((void**)&g, g_g);
    cudaGetSymbolAddress((void**)&o, g_o);
    cudaGetSymbolAddress((void**)&beta, g_beta);
    cudaGetSymbolAddress((void**)&dec, g_dec);
    __nv_bfloat16 *xh, *xl, *yh, *yl, *wth, *wtl;
    cudaGetSymbolAddress((void**)&xh, g_xh);
    cudaGetSymbolAddress((void**)&xl, g_xl);
    cudaGetSymbolAddress((void**)&yh, g_yh);
    cudaGetSymbolAddress((void**)&yl, g_yl);
    cudaGetSymbolAddress((void**)&wth, g_wth);
    cudaGetSymbolAddress((void**)&wtl, g_wtl);

    cudaFuncSetAttribute(gemm_mma_bf16x3,
                         cudaFuncAttributeMaxDynamicSharedMemorySize,
                         GEMM_SMEM);

    dim3 tgrid(Dsz / 32, Dsz / 32);
    transpose_split_kernel<<<tgrid, 256>>>(Wq, wth + 0*Dsz*Dsz, wtl + 0*Dsz*Dsz);
    transpose_split_kernel<<<tgrid, 256>>>(Wk, wth + 1*Dsz*Dsz, wtl + 1*Dsz*Dsz);
    transpose_split_kernel<<<tgrid, 256>>>(Wv, wth + 2*Dsz*Dsz, wtl + 2*Dsz*Dsz);
    transpose_split_kernel<<<tgrid, 256>>>(Wg, wth + 3*Dsz*Dsz, wtl + 3*Dsz*Dsz);
    transpose_split_kernel<<<tgrid, 256>>>(Wo, wth + 4*Dsz*Dsz, wtl + 4*Dsz*Dsz);
    split_kernel<<<(ROWS * Dsz / 4) / 256, 256>>>(x, xh, xl);

    dim3 ggrid(Dsz / 128, ROWS / 128);
    gemm_mma_bf16x3<<<ggrid, 256, GEMM_SMEM>>>(xh, xl, wth + 0*Dsz*Dsz, wtl + 0*Dsz*Dsz, q);
    gemm_mma_bf16x3<<<ggrid, 256, GEMM_SMEM>>>(xh, xl, wth + 1*Dsz*Dsz, wtl + 1*Dsz*Dsz, k);
    gemm_mma_bf16x3<<<ggrid, 256, GEMM_SMEM>>>(xh, xl, wth + 2*Dsz*Dsz, wtl + 2*Dsz*Dsz, v);
    gemm_mma_bf16x3<<<ggrid, 256, GEMM_SMEM>>>(xh, xl, wth + 3*Dsz*Dsz, wtl + 3*Dsz*Dsz, g);

    beta_dec_kernel<<<ROWS / 8, 256>>>(x, Wb, Wa, A_log, dt_bias, beta, dec);
    norm_qk_kernel<<<(ROWS * Hsz) / 8, 256>>>(q, k);

    recurrence_kernel<<<Bsz * Hsz * 32, 256>>>(q, k, v, beta, dec, o);

    gate_norm_kernel<<<(ROWS * Hsz) / 8, 256>>>(o, g, norm_w, q);
    split_kernel<<<(ROWS * Dsz / 4) / 256, 256>>>(q, yh, yl);
    gemm_mma_bf16x3<<<ggrid, 256, GEMM_SMEM>>>(yh, yl, wth + 4*Dsz*Dsz, wtl + 4*Dsz*Dsz, out);
}

// round 7
// speedup vs baseline: 1.6448x; 1.0002x over previous
#include <cuda_runtime.h>
#include <cuda_bf16.h>
#include <math.h>
#include <cstdint>

// Problem constants
#define Bsz 4
#define Tsz 4096
#define Dsz 1024
#define Hsz 4
#define DKsz 256
#define DVsz 256
#define ROWS (Bsz*Tsz)        // 16384
#define STEPS 16

// -------- static device scratch (no allocations allowed) --------
__device__ float g_q[ROWS * Dsz];
__device__ float g_k[ROWS * Dsz];
__device__ float g_v[ROWS * Dsz];
__device__ float g_g[ROWS * Dsz];
__device__ float g_o[ROWS * Dsz];
__device__ float g_beta[ROWS * Hsz];
__device__ float g_dec[ROWS * Hsz];
// bf16 split operands
__device__ __nv_bfloat16 g_xh[ROWS * Dsz];
__device__ __nv_bfloat16 g_xl[ROWS * Dsz];
__device__ __nv_bfloat16 g_yh[ROWS * Dsz];
__device__ __nv_bfloat16 g_yl[ROWS * Dsz];
__device__ __nv_bfloat16 g_wth[5 * Dsz * Dsz];
__device__ __nv_bfloat16 g_wtl[5 * Dsz * Dsz];

// ============================================================
// helpers (baseline PTX only)
// ============================================================
__device__ __forceinline__ uint32_t smem_to_u32(const void* p) {
    uint32_t a;
    asm("{ .reg .u64 t; cvta.to.shared.u64 t, %1; cvt.u32.u64 %0, t; }"
        : "=r"(a) : "l"(p));
    return a;
}
__device__ __forceinline__ void cp_async16(uint32_t s, const void* g) {
    asm volatile("cp.async.cg.shared.global [%0], [%1], 16;" :: "r"(s), "l"(g));
}
__device__ __forceinline__ void ldsm4(uint32_t& r0, uint32_t& r1, uint32_t& r2,
                                      uint32_t& r3, uint32_t addr) {
    asm volatile("ldmatrix.sync.aligned.m8n8.x4.shared.b16 {%0,%1,%2,%3}, [%4];"
                 : "=r"(r0), "=r"(r1), "=r"(r2), "=r"(r3) : "r"(addr));
}
__device__ __forceinline__ void mma16816(float* c, const uint32_t* a,
                                         uint32_t b0, uint32_t b1) {
    asm volatile(
        "mma.sync.aligned.m16n8k16.row.col.f32.bf16.bf16.f32 "
        "{%0,%1,%2,%3}, {%4,%5,%6,%7}, {%8,%9}, {%0,%1,%2,%3};"
        : "+f"(c[0]), "+f"(c[1]), "+f"(c[2]), "+f"(c[3])
        : "r"(a[0]), "r"(a[1]), "r"(a[2]), "r"(a[3]), "r"(b0), "r"(b1));
}
// ---- packed f32x2 (sm_100+ base ISA) ----
typedef unsigned long long u64t;
__device__ __forceinline__ u64t pack2(float x) {
    u64t r;
    asm("mov.b64 %0, {%1, %1};" : "=l"(r) : "f"(x));
    return r;
}
__device__ __forceinline__ void fma2(u64t& d, u64t a, u64t b, u64t c) {
    asm("fma.rn.f32x2 %0, %1, %2, %3;" : "=l"(d) : "l"(a), "l"(b), "l"(c));
}
__device__ __forceinline__ void mul2(u64t& d, u64t a, u64t b) {
    asm("mul.rn.f32x2 %0, %1, %2;" : "=l"(d) : "l"(a), "l"(b));
}
__device__ __forceinline__ void add2(u64t& d, u64t a, u64t b) {
    asm("add.rn.f32x2 %0, %1, %2;" : "=l"(d) : "l"(a), "l"(b));
}
__device__ __forceinline__ float sum2(u64t a) {
    float lo, hi;
    asm("mov.b64 {%0, %1}, %2;" : "=f"(lo), "=f"(hi) : "l"(a));
    return lo + hi;
}

// ============================================================
// fp32 -> (hi, lo) bf16 split
// ============================================================
__global__ __launch_bounds__(256) void split_kernel(
    const float* __restrict__ src, __nv_bfloat16* __restrict__ hi,
    __nv_bfloat16* __restrict__ lo)
{
    const int i = blockIdx.x * 256 + threadIdx.x;
    float4 v = ((const float4*)src)[i];
    __nv_bfloat16 h0 = __float2bfloat16(v.x), h1 = __float2bfloat16(v.y);
    __nv_bfloat16 h2 = __float2bfloat16(v.z), h3 = __float2bfloat16(v.w);
    __nv_bfloat16 l0 = __float2bfloat16(v.x - __bfloat162float(h0));
    __nv_bfloat16 l1 = __float2bfloat16(v.y - __bfloat162float(h1));
    __nv_bfloat16 l2 = __float2bfloat16(v.z - __bfloat162float(h2));
    __nv_bfloat16 l3 = __float2bfloat16(v.w - __bfloat162float(h3));
    ((__nv_bfloat162*)hi)[i*2]   = __halves2bfloat162(h0, h1);
    ((__nv_bfloat162*)hi)[i*2+1] = __halves2bfloat162(h2, h3);
    ((__nv_bfloat162*)lo)[i*2]   = __halves2bfloat162(l0, l1);
    ((__nv_bfloat162*)lo)[i*2+1] = __halves2bfloat162(l2, l3);
}

// ============================================================
// transpose 1024x1024 fp32 weight, split into hi/lo bf16
// ============================================================
__global__ __launch_bounds__(256) void transpose_split_kernel(
    const float* __restrict__ W, __nv_bfloat16* __restrict__ Th,
    __nv_bfloat16* __restrict__ Tl)
{
    __shared__ float tile[32][33];
    const int n0 = blockIdx.x * 32, k0 = blockIdx.y * 32;
    const int tx = threadIdx.x & 31, ty = threadIdx.x >> 5;
#pragma unroll
    for (int r = ty; r < 32; r += 8)
        tile[r][tx] = W[(size_t)(k0 + r) * Dsz + n0 + tx];
    __syncthreads();
#pragma unroll
    for (int r = ty; r < 32; r += 8) {
        float v = tile[tx][r];
        __nv_bfloat16 h = __float2bfloat16(v);
        __nv_bfloat16 l = __float2bfloat16(v - __bfloat162float(h));
        size_t o = (size_t)(n0 + r) * Dsz + k0 + tx;
        Th[o] = h;
        Tl[o] = l;
    }
}

// ============================================================
// bf16x3 GEMM via mma.sync (unchanged from R3)
// ============================================================
#define TILE_BYTES (128*80)
#define STAGE_BYTES (4*TILE_BYTES)
#define GEMM_SMEM (2*STAGE_BYTES)

__global__ __launch_bounds__(256, 1) void gemm_mma_bf16x3(
    const __nv_bfloat16* __restrict__ Ah, const __nv_bfloat16* __restrict__ Al,
    const __nv_bfloat16* __restrict__ Bh, const __nv_bfloat16* __restrict__ Bl,
    float* __restrict__ C)
{
    extern __shared__ char sm[];
    const int tid = threadIdx.x;
    const int wid = tid >> 5, lane = tid & 31;
    const int bx = blockIdx.x, by = blockIdx.y;
    const int wm = wid & 3;
    const int wn = wid >> 2;

    const uint32_t sbase = smem_to_u32(sm);

    const __nv_bfloat16* srcs[4] = {
        Ah + (size_t)(by * 128) * Dsz,
        Al + (size_t)(by * 128) * Dsz,
        Bh + (size_t)(bx * 128) * Dsz,
        Bl + (size_t)(bx * 128) * Dsz
    };

    float acc[2][8][4];
#pragma unroll
    for (int mt = 0; mt < 2; mt++)
#pragma unroll
        for (int nt = 0; nt < 8; nt++)
#pragma unroll
            for (int i = 0; i < 4; i++) acc[mt][nt][i] = 0.f;

    auto load_stage = [&](int kc) {
        const uint32_t sdst = sbase + (kc & 1) * STAGE_BYTES;
        const int k0 = kc * 32;
#pragma unroll
        for (int t = 0; t < 4; t++) {
            const __nv_bfloat16* src = srcs[t];
#pragma unroll
            for (int i = 0; i < 2; i++) {
                int id = i * 256 + tid;
                int r = id >> 2, c = id & 3;
                cp_async16(sdst + t * TILE_BYTES + r * 80 + c * 16,
                           src + (size_t)r * Dsz + k0 + c * 8);
            }
        }
        asm volatile("cp.async.commit_group;" ::: "memory");
    };

    load_stage(0);

    const int lrow = lane & 15;
    const int lcolb = (lane >> 4) * 16;

    for (int kc = 0; kc < 32; kc++) {
        if (kc < 31) load_stage(kc + 1);
        else asm volatile("cp.async.commit_group;" ::: "memory");
        asm volatile("cp.async.wait_group 1;" ::: "memory");
        __syncthreads();

        const uint32_t s = sbase + (kc & 1) * STAGE_BYTES;
        const uint32_t sAh = s;
        const uint32_t sAl = s + TILE_BYTES;
        const uint32_t sBh = s + 2 * TILE_BYTES;
        const uint32_t sBl = s + 3 * TILE_BYTES;

#pragma unroll
        for (int ks = 0; ks < 2; ks++) {
            const uint32_t cb = ks * 32 + lcolb;
            uint32_t ah[2][4], bh[4][4], al[2][4], bl[4][4];
#pragma unroll
            for (int mt = 0; mt < 2; mt++)
                ldsm4(ah[mt][0], ah[mt][1], ah[mt][2], ah[mt][3],
                      sAh + (wm * 32 + mt * 16 + lrow) * 80 + cb);
#pragma unroll
            for (int bt = 0; bt < 4; bt++)
                ldsm4(bh[bt][0], bh[bt][1], bh[bt][2], bh[bt][3],
                      sBh + (wn * 64 + bt * 16 + lrow) * 80 + cb);
#pragma unroll
            for (int mt = 0; mt < 2; mt++)
#pragma unroll
                for (int bt = 0; bt < 4; bt++) {
                    mma16816(acc[mt][bt*2],   ah[mt], bh[bt][0], bh[bt][2]);
                    mma16816(acc[mt][bt*2+1], ah[mt], bh[bt][1], bh[bt][3]);
                }
#pragma unroll
            for (int mt = 0; mt < 2; mt++)
                ldsm4(al[mt][0], al[mt][1], al[mt][2], al[mt][3],
                      sAl + (wm * 32 + mt * 16 + lrow) * 80 + cb);
#pragma unroll
            for (int mt = 0; mt < 2; mt++)
#pragma unroll
                for (int bt = 0; bt < 4; bt++) {
                    mma16816(acc[mt][bt*2],   al[mt], bh[bt][0], bh[bt][2]);
                    mma16816(acc[mt][bt*2+1], al[mt], bh[bt][1], bh[bt][3]);
                }
#pragma unroll
            for (int bt = 0; bt < 4; bt++)
                ldsm4(bl[bt][0], bl[bt][1], bl[bt][2], bl[bt][3],
                      sBl + (wn * 64 + bt * 16 + lrow) * 80 + cb);
#pragma unroll
            for (int mt = 0; mt < 2; mt++)
#pragma unroll
                for (int bt = 0; bt < 4; bt++) {
                    mma16816(acc[mt][bt*2],   ah[mt], bl[bt][0], bl[bt][2]);
                    mma16816(acc[mt][bt*2+1], ah[mt], bl[bt][1], bl[bt][3]);
                }
        }
        __syncthreads();
    }

    const int crow = by * 128 + wm * 32 + (lane >> 2);
    const int ccol = bx * 128 + wn * 64 + (lane & 3) * 2;
#pragma unroll
    for (int mt = 0; mt < 2; mt++) {
#pragma unroll
        for (int nt = 0; nt < 8; nt++) {
            float* p0 = C + (size_t)(crow + mt * 16) * Dsz + ccol + nt * 8;
            float* p1 = p0 + 8 * Dsz;
            *(float2*)p0 = make_float2(acc[mt][nt][0], acc[mt][nt][1]);
            *(float2*)p1 = make_float2(acc[mt][nt][2], acc[mt][nt][3]);
        }
    }
}

// ============================================================
// beta / dec projections (unchanged)
// ============================================================
__global__ __launch_bounds__(256) void beta_dec_kernel(
    const float* __restrict__ x, const float* __restrict__ Wb,
    const float* __restrict__ Wa, const float* __restrict__ A_log,
    const float* __restrict__ dt_bias,
    float* __restrict__ beta, float* __restrict__ dec)
{
    const int row = blockIdx.x * 8 + (threadIdx.x >> 5);
    const int lane = threadIdx.x & 31;
    if (row >= ROWS) return;

    float accb[4] = {0,0,0,0}, acca[4] = {0,0,0,0};
    const float* xr = x + (size_t)row * Dsz;
    const float4* Wb4 = (const float4*)Wb;
    const float4* Wa4 = (const float4*)Wa;

    for (int i = lane; i < Dsz; i += 32) {
        float xv = xr[i];
        float4 wb = Wb4[i];
        float4 wa = Wa4[i];
        accb[0] += xv * wb.x; accb[1] += xv * wb.y;
        accb[2] += xv * wb.z; accb[3] += xv * wb.w;
        acca[0] += xv * wa.x; acca[1] += xv * wa.y;
        acca[2] += xv * wa.z; acca[3] += xv * wa.w;
    }
#pragma unroll
    for (int off = 16; off; off >>= 1) {
#pragma unroll
        for (int h = 0; h < 4; h++) {
            accb[h] += __shfl_xor_sync(0xffffffffu, accb[h], off);
            acca[h] += __shfl_xor_sync(0xffffffffu, acca[h], off);
        }
    }
    if (lane < 4) {
        int h = lane;
        float bv = 1.f / (1.f + expf(-accb[h]));
        float a = acca[h] + dt_bias[h];
        float sp = fmaxf(a, 0.f) + log1pf(expf(-fabsf(a)));
        float dv = expf(-expf(A_log[h]) * sp);
        beta[(size_t)row * Hsz + h] = bv;
        dec [(size_t)row * Hsz + h] = dv;
    }
}

// ============================================================
// L2-normalize q and k (unchanged)
// ============================================================
__global__ __launch_bounds__(256) void norm_qk_kernel(float* __restrict__ q,
                                                      float* __restrict__ k)
{
    const int row = blockIdx.x * 8 + (threadIdx.x >> 5);
    const int lane = threadIdx.x & 31;
    float4* qr = (float4*)(q + (size_t)row * DKsz);
    float4* kr = (float4*)(k + (size_t)row * DKsz);
    float4 q0 = qr[lane * 2], q1 = qr[lane * 2 + 1];
    float4 k0 = kr[lane * 2], k1 = kr[lane * 2 + 1];

    float sq = q0.x*q0.x + q0.y*q0.y + q0.z*q0.z + q0.w*q0.w
             + q1.x*q1.x + q1.y*q1.y + q1.z*q1.z + q1.w*q1.w;
    float sk = k0.x*k0.x + k0.y*k0.y + k0.z*k0.z + k0.w*k0.w
             + k1.x*k1.x + k1.y*k1.y + k1.z*k1.z + k1.w*k1.w;
#pragma unroll
    for (int off = 16; off; off >>= 1) {
        sq += __shfl_xor_sync(0xffffffffu, sq, off);
        sk += __shfl_xor_sync(0xffffffffu, sk, off);
    }
    float qs = rsqrtf(sq + 1e-6f) * 0.0625f;
    float ks = rsqrtf(sk + 1e-6f);
    q0.x*=qs; q0.y*=qs; q0.z*=qs; q0.w*=qs;
    q1.x*=qs; q1.y*=qs; q1.z*=qs; q1.w*=qs;
    k0.x*=ks; k0.y*=ks; k0.z*=ks; k0.w*=ks;
    k1.x*=ks; k1.y*=ks; k1.z*=ks; k1.w*=ks;
    qr[lane * 2] = q0; qr[lane * 2 + 1] = q1;
    kr[lane * 2] = k0; kr[lane * 2 + 1] = k1;
}

// ============================================================
// Gated delta-rule recurrence — R3 algorithm, f32x2-packed math,
// contiguous-row state layout (lane owns rows lane*4..+3 and
// 128+lane*4..+3) so k/q tile reads are 4 conflict-free LDS.128.
// ============================================================
__global__ __launch_bounds__(256) void recurrence_kernel(
    const float* __restrict__ q, const float* __restrict__ k,
    const float* __restrict__ v, const float* __restrict__ beta,
    const float* __restrict__ dec, float* __restrict__ o)
{
    const int cta = blockIdx.x;       // 512
    const int bh = cta >> 5;          // 0..15
    const int jg = cta & 31;          // column group
    const int b = bh >> 2, h = bh & 3;
    const int w = threadIdx.x >> 5, lane = threadIdx.x & 31;
    const int j = jg * 8 + w;

    __shared__ float sk[STEPS][DKsz];
    __shared__ float sq[STEPS][DKsz];
    __shared__ float sv[STEPS][8];
    __shared__ float sb[STEPS], sd[STEPS];

    // state: rows lane*4..+3 in s2[0..1], rows 128+lane*4..+3 in s2[2..3]
    u64t s2[4] = {0ull, 0ull, 0ull, 0ull};

    const size_t rowbase = (size_t)b * Tsz * Dsz + h * DKsz;
    const int ro0 = lane * 4;           // first row block (float index)
    const int ro1 = 128 + lane * 4;     // second row block

    for (int t0 = 0; t0 < Tsz; t0 += STEPS) {
        __syncthreads();
        // cooperative load of k/q tiles: 16 steps x 256 floats each
#pragma unroll
        for (int r = 0; r < 4; r++) {
            int idx = r * 256 + threadIdx.x;
            int ss = idx >> 6;
            int d4 = (idx & 63) * 4;
            size_t gaddr = rowbase + (size_t)(t0 + ss) * Dsz + d4;
            *(float4*)&sk[ss][d4] = *(const float4*)(k + gaddr);
            *(float4*)&sq[ss][d4] = *(const float4*)(q + gaddr);
        }
        if (threadIdx.x < 128) {
            int ss = threadIdx.x >> 3, jj = threadIdx.x & 7;
            sv[ss][jj] = v[rowbase + (size_t)(t0 + ss) * Dsz + jg * 8 + jj];
        }
        if (threadIdx.x < STEPS) {
            size_t bidx = (size_t)(b * Tsz + t0 + threadIdx.x) * Hsz + h;
            sb[threadIdx.x] = beta[bidx];
            sd[threadIdx.x] = dec[bidx];
        }
        __syncthreads();

#pragma unroll 4
        for (int ss = 0; ss < STEPS; ss++) {
            const float de = sd[ss], be = sb[ss], vj = sv[ss][w];
            // k slices (2x LDS.128, conflict-free)
            const ulonglong2 ka = *(const ulonglong2*)&sk[ss][ro0];
            const ulonglong2 kb = *(const ulonglong2*)&sk[ss][ro1];
            // p_partial = k . s   (packed; decay folded in after reduce)
            u64t a0, a1;
            mul2(a0, ka.x, s2[0]); fma2(a0, ka.y, s2[1], a0);
            mul2(a1, kb.x, s2[2]); fma2(a1, kb.y, s2[3], a1);
            add2(a0, a0, a1);
            float p = sum2(a0);
#pragma unroll
            for (int off = 16; off; off >>= 1)
                p += __shfl_xor_sync(0xffffffffu, p, off);
            // u = beta * (v - de * (k . S_old))   [S decayed by de]
            const float u = be * fmaf(-de, p, vj);
            const u64t dd = pack2(de);
            const u64t uu = pack2(u);
            // s = de*s + k*u
            mul2(s2[0], s2[0], dd); fma2(s2[0], ka.x, uu, s2[0]);
            mul2(s2[1], s2[1], dd); fma2(s2[1], ka.y, uu, s2[1]);
            mul2(s2[2], s2[2], dd); fma2(s2[2], kb.x, uu, s2[2]);
            mul2(s2[3], s2[3], dd); fma2(s2[3], kb.y, uu, s2[3]);
            // o = q . s
            const ulonglong2 qa = *(const ulonglong2*)&sq[ss][ro0];
            const ulonglong2 qb = *(const ulonglong2*)&sq[ss][ro1];
            u64t b0, b1;
            mul2(b0, qa.x, s2[0]); fma2(b0, qa.y, s2[1], b0);
            mul2(b1, qb.x, s2[2]); fma2(b1, qb.y, s2[3], b1);
            add2(b0, b0, b1);
            float ov = sum2(b0);
#pragma unroll
            for (int off = 16; off; off >>= 1)
                ov += __shfl_xor_sync(0xffffffffu, ov, off);
            if (lane == 0)
                o[rowbase + (size_t)(t0 + ss) * Dsz + j] = ov;
        }
    }
}

// ============================================================
// Gated RMSNorm (unchanged)
// ============================================================
__global__ __launch_bounds__(256) void gate_norm_kernel(
    const float* __restrict__ o, const float* __restrict__ g,
    const float* __restrict__ norm_w, float* __restrict__ out)
{
    const int row = blockIdx.x * 8 + (threadIdx.x >> 5);
    const int lane = threadIdx.x & 31;
    const float4* orow = (const float4*)(o + (size_t)row * DVsz);
    float4 o0 = orow[lane * 2], o1 = orow[lane * 2 + 1];

    float ss = o0.x*o0.x + o0.y*o0.y + o0.z*o0.z + o0.w*o0.w
             + o1.x*o1.x + o1.y*o1.y + o1.z*o1.z + o1.w*o1.w;
#pragma unroll
    for (int off = 16; off; off >>= 1)
        ss += __shfl_xor_sync(0xffffffffu, ss, off);
    float r = rsqrtf(ss * (1.f / 256.f) + 1e-5f);

    const float4* nw = (const float4*)norm_w;
    float4 w0 = nw[lane * 2], w1 = nw[lane * 2 + 1];
    const float4* grow = (const float4*)(g + (size_t)row * DVsz);
    float4 g0 = grow[lane * 2], g1 = grow[lane * 2 + 1];

    float4 r0, r1;
    r0.x = o0.x * r * w0.x * (g0.x / (1.f + expf(-g0.x)));
    r0.y = o0.y * r * w0.y * (g0.y / (1.f + expf(-g0.y)));
    r0.z = o0.z * r * w0.z * (g0.z / (1.f + expf(-g0.z)));
    r0.w = o0.w * r * w0.w * (g0.w / (1.f + expf(-g0.w)));
    r1.x = o1.x * r * w1.x * (g1.x / (1.f + expf(-g1.x)));
    r1.y = o1.y * r * w1.y * (g1.y / (1.f + expf(-g1.y)));
    r1.z = o1.z * r * w1.z * (g1.z / (1.f + expf(-g1.z)));
    r1.w = o1.w * r * w1.w * (g1.w / (1.f + expf(-g1.w)));

    float4* outr = (float4*)(out + (size_t)row * DVsz);
    outr[lane * 2] = r0;
    outr[lane * 2 + 1] = r1;
}

// ============================================================
// host launch
// ============================================================
extern "C" void kernel_launch(void* const* d_in, const int* in_sizes, int n_in,
                              void* d_out, int out_size)
{
    const float* x       = (const float*)d_in[0];
    const float* Wq      = (const float*)d_in[1];
    const float* Wk      = (const float*)d_in[2];
    const float* Wv      = (const float*)d_in[3];
    const float* Wb      = (const float*)d_in[4];
    const float* Wa      = (const float*)d_in[5];
    const float* A_log   = (const float*)d_in[6];
    const float* dt_bias = (const float*)d_in[7];
    const float* Wg      = (const float*)d_in[8];
    const float* norm_w  = (const float*)d_in[9];
    const float* Wo      = (const float*)d_in[10];
    float* out = (float*)d_out;

    float *q, *k, *v, *g, *o, *beta, *dec;
    cudaGetSymbolAddress((void**)&q, g_q);
    cudaGetSymbolAddress((void**)&k, g_k);
    cudaGetSymbolAddress((void**)&v, g_v);
    cudaGetSymbolAddress((void**)&g, g_g);
    cudaGetSymbolAddress((void**)&o, g_o);
    cudaGetSymbolAddress((void**)&beta, g_beta);
    cudaGetSymbolAddress((void**)&dec, g_dec);
    __nv_bfloat16 *xh, *xl, *yh, *yl, *wth, *wtl;
    cudaGetSymbolAddress((void**)&xh, g_xh);
    cudaGetSymbolAddress((void**)&xl, g_xl);
    cudaGetSymbolAddress((void**)&yh, g_yh);
    cudaGetSymbolAddress((void**)&yl, g_yl);
    cudaGetSymbolAddress((void**)&wth, g_wth);
    cudaGetSymbolAddress((void**)&wtl, g_wtl);

    cudaFuncSetAttribute(gemm_mma_bf16x3,
                         cudaFuncAttributeMaxDynamicSharedMemorySize,
                         GEMM_SMEM);

    dim3 tgrid(Dsz / 32, Dsz / 32);
    transpose_split_kernel<<<tgrid, 256>>>(Wq, wth + 0*Dsz*Dsz, wtl + 0*Dsz*Dsz);
    transpose_split_kernel<<<tgrid, 256>>>(Wk, wth + 1*Dsz*Dsz, wtl + 1*Dsz*Dsz);
    transpose_split_kernel<<<tgrid, 256>>>(Wv, wth + 2*Dsz*Dsz, wtl + 2*Dsz*Dsz);
    transpose_split_kernel<<<tgrid, 256>>>(Wg, wth + 3*Dsz*Dsz, wtl + 3*Dsz*Dsz);
    transpose_split_kernel<<<tgrid, 256>>>(Wo, wth + 4*Dsz*Dsz, wtl + 4*Dsz*Dsz);
    split_kernel<<<(ROWS * Dsz / 4) / 256, 256>>>(x, xh, xl);

    dim3 ggrid(Dsz / 128, ROWS / 128);
    gemm_mma_bf16x3<<<ggrid, 256, GEMM_SMEM>>>(xh, xl, wth + 0*Dsz*Dsz, wtl + 0*Dsz*Dsz, q);
    gemm_mma_bf16x3<<<ggrid, 256, GEMM_SMEM>>>(xh, xl, wth + 1*Dsz*Dsz, wtl + 1*Dsz*Dsz, k);
    gemm_mma_bf16x3<<<ggrid, 256, GEMM_SMEM>>>(xh, xl, wth + 2*Dsz*Dsz, wtl + 2*Dsz*Dsz, v);
    gemm_mma_bf16x3<<<ggrid, 256, GEMM_SMEM>>>(xh, xl, wth + 3*Dsz*Dsz, wtl + 3*Dsz*Dsz, g);

    beta_dec_kernel<<<ROWS / 8, 256>>>(x, Wb, Wa, A_log, dt_bias, beta, dec);
    norm_qk_kernel<<<(ROWS * Hsz) / 8, 256>>>(q, k);

    recurrence_kernel<<<Bsz * Hsz * 32, 256>>>(q, k, v, beta, dec, o);

    gate_norm_kernel<<<(ROWS * Hsz) / 8, 256>>>(o, g, norm_w, q);
    split_kernel<<<(ROWS * Dsz / 4) / 256, 256>>>(q, yh, yl);
    gemm_mma_bf16x3<<<ggrid, 256, GEMM_SMEM>>>(yh, yl, wth + 4*Dsz*Dsz, wtl + 4*Dsz*Dsz, out);
}